// round 1
// baseline (speedup 1.0000x reference)
#include <cuda_runtime.h>

#define NN 12800          // nodes
#define NE 409600         // edges
#define FEAT 200
#define HID 256
#define NG 64             // graphs
#define RDK 51200         // 200*256 readout K

// ---------------- static device scratch (no allocs allowed) ----------------
__device__ int   g_src[NE];
__device__ int   g_dst[NE];
__device__ int   g_cnt[NN];
__device__ int   g_rowptr[NN + 1];
__device__ int   g_cursor[NN];
__device__ int   g_degp[NN];
__device__ int   g_degn[NN];
__device__ float g_invdegp[NN];
__device__ float g_invdegn[NN];
__device__ int   g_esrc[NE];
__device__ float g_ews[NE];
__device__ float g_h1[NN * HID];
__device__ float g_h2[NN * HID];
__device__ float g_proj[(size_t)NN * 512];
__device__ float g_B[256 * 512];      // packed weight, K-major (K<=256, M=512)
__device__ float g_bias[512];
__device__ float g_g[NG * HID];

// ---------------- edge decode: int64 vs int32 probe ----------------
__global__ void k_decode(const int* __restrict__ ei) {
    // If stored as int64: values < 12800 and >= 0, so every odd int32 word is 0.
    bool is64 = ((ei[1] | ei[3] | ei[5] | ei[7] | ei[9] | ei[11] | ei[13] | ei[15]) == 0);
    int e = blockIdx.x * blockDim.x + threadIdx.x;
    if (e >= NE) return;
    if (is64) {
        const long long* q = (const long long*)ei;
        g_src[e] = (int)q[e];
        g_dst[e] = (int)q[NE + e];
    } else {
        g_src[e] = ei[e];
        g_dst[e] = ei[NE + e];
    }
}

__global__ void k_zero_nodes() {
    int i = blockIdx.x * blockDim.x + threadIdx.x;
    if (i < NN) { g_cnt[i] = 0; g_degp[i] = 0; g_degn[i] = 0; }
}

__global__ void k_hist(const float* __restrict__ w) {
    int e = blockIdx.x * blockDim.x + threadIdx.x;
    if (e >= NE) return;
    int d = g_dst[e];
    atomicAdd(&g_cnt[d], 1);
    float we = w[e];
    if (we > 0.f)      atomicAdd(&g_degp[d], 1);
    else if (we < 0.f) atomicAdd(&g_degn[d], 1);
}

// single-block exclusive scan over 12800 counts + invdeg
__global__ void k_scan() {
    __shared__ int ss[1024];
    const int CH = 13;                      // 1024*13 >= 12800
    int t = threadIdx.x;
    int base = t * CH;
    int loc[CH];
    int s = 0;
#pragma unroll
    for (int i = 0; i < CH; i++) {
        int idx = base + i;
        int c = (idx < NN) ? g_cnt[idx] : 0;
        loc[i] = s; s += c;
    }
    ss[t] = s; __syncthreads();
    for (int off = 1; off < 1024; off <<= 1) {
        int v = (t >= off) ? ss[t - off] : 0;
        __syncthreads();
        if (t >= off) ss[t] += v;
        __syncthreads();
    }
    int ex = (t == 0) ? 0 : ss[t - 1];
#pragma unroll
    for (int i = 0; i < CH; i++) {
        int idx = base + i;
        if (idx < NN) { int r = ex + loc[i]; g_rowptr[idx] = r; g_cursor[idx] = r; }
    }
    if (t == 0) g_rowptr[NN] = NE;
    for (int i = t; i < NN; i += 1024) {
        g_invdegp[i] = 1.f / fmaxf((float)g_degp[i], 1.f);
        g_invdegn[i] = 1.f / fmaxf((float)g_degn[i], 1.f);
    }
}

__global__ void k_scatter(const float* __restrict__ w) {
    int e = blockIdx.x * blockDim.x + threadIdx.x;
    if (e >= NE) return;
    int d = g_dst[e];
    int pos = atomicAdd(&g_cursor[d], 1);
    g_esrc[pos] = g_src[e];
    g_ews[pos]  = w[e];
}

// ---------------- pack per-layer weights into K-major [K x 512] ----------------
// cols 0..127: Wp agg-part, 128..255: Wn agg-part, 256..383: Wp x-part(+bp), 384..511: Wn x-part(+bn)
__global__ void k_pack(const float* __restrict__ Wp, const float* __restrict__ Wn,
                       const float* __restrict__ bp, const float* __restrict__ bn, int D) {
    int idx = blockIdx.x * blockDim.x + threadIdx.x;
    if (idx >= D * 512) return;
    int k = idx >> 9, m = idx & 511;
    int twoD = 2 * D;
    float v;
    if (m < 128)       v = Wp[m * twoD + k];
    else if (m < 256)  v = Wn[(m - 128) * twoD + k];
    else if (m < 384)  v = Wp[(m - 256) * twoD + D + k];
    else               v = Wn[(m - 384) * twoD + D + k];
    g_B[k * 512 + m] = v;
    if (k == 0)
        g_bias[m] = (m < 256) ? 0.f : ((m < 384) ? bp[m - 256] : bn[m - 384]);
}

// ---------------- GEMM: proj[NN x 512] = A[NN x K] @ g_B[K x 512] + g_bias ----------------
// BM=128, BN=64, BK=16, 256 threads, 8x4 per thread
__global__ void __launch_bounds__(256) k_gemm(const float* __restrict__ Ax, int asel, int K) {
    const float* __restrict__ A = (asel == 0) ? Ax : ((asel == 1) ? g_h1 : g_h2);
    __shared__ float As[16][128];
    __shared__ float Bs[16][64];
    int tid = threadIdx.x;
    int row0 = blockIdx.y * 128;
    int col0 = blockIdx.x * 64;
    int ty = tid >> 4, tx = tid & 15;

    int aRow = tid >> 1;
    int aK   = (tid & 1) * 8;
    int bK   = tid >> 4;
    int bC   = (tid & 15) * 4;

    float acc[8][4];
#pragma unroll
    for (int i = 0; i < 8; i++)
#pragma unroll
        for (int j = 0; j < 4; j++) acc[i][j] = 0.f;

    for (int k0 = 0; k0 < K; k0 += 16) {
        const float* Ap = A + (size_t)(row0 + aRow) * K + k0 + aK;
#pragma unroll
        for (int i = 0; i < 8; i++) {
            float v = (k0 + aK + i < K) ? Ap[i] : 0.f;
            As[aK + i][aRow] = v;
        }
        float4 bv = make_float4(0.f, 0.f, 0.f, 0.f);
        if (k0 + bK < K) bv = *(const float4*)(g_B + (size_t)(k0 + bK) * 512 + col0 + bC);
        *(float4*)&Bs[bK][bC] = bv;
        __syncthreads();
#pragma unroll
        for (int kk = 0; kk < 16; kk++) {
            float4 a0 = *(const float4*)&As[kk][ty * 8];
            float4 a1 = *(const float4*)&As[kk][ty * 8 + 4];
            float4 b  = *(const float4*)&Bs[kk][tx * 4];
            float av[8] = {a0.x, a0.y, a0.z, a0.w, a1.x, a1.y, a1.z, a1.w};
            float bw[4] = {b.x, b.y, b.z, b.w};
#pragma unroll
            for (int i = 0; i < 8; i++)
#pragma unroll
                for (int j = 0; j < 4; j++) acc[i][j] += av[i] * bw[j];
        }
        __syncthreads();
    }
    int col = col0 + tx * 4;
    float4 bb = *(const float4*)&g_bias[col];
#pragma unroll
    for (int i = 0; i < 8; i++) {
        int row = row0 + ty * 8 + i;
        float4 o;
        o.x = acc[i][0] + bb.x; o.y = acc[i][1] + bb.y;
        o.z = acc[i][2] + bb.z; o.w = acc[i][3] + bb.w;
        *(float4*)(g_proj + (size_t)row * 512 + col) = o;
    }
}

// ---------------- per-node signed mean aggregation + combine (+leaky relu) ----------------
// one warp per node; lane handles 4 contiguous cols via float4
__global__ void k_agg(int outsel, int lrelu) {
    float* __restrict__ hout = (outsel == 1) ? g_h1 : g_h2;
    int gw = (blockIdx.x * blockDim.x + threadIdx.x) >> 5;
    if (gw >= NN) return;
    int lane = threadIdx.x & 31;
    int co = lane * 4;
    int s0 = g_rowptr[gw], s1 = g_rowptr[gw + 1];
    float4 ap = make_float4(0, 0, 0, 0), an = make_float4(0, 0, 0, 0);
    for (int e = s0; e < s1; e++) {
        int s = g_esrc[e];
        float w = g_ews[e];
        if (w > 0.f) {
            float4 v = *(const float4*)(g_proj + (size_t)s * 512 + co);
            ap.x += w * v.x; ap.y += w * v.y; ap.z += w * v.z; ap.w += w * v.w;
        } else {
            float4 v = *(const float4*)(g_proj + (size_t)s * 512 + 128 + co);
            float a = -w;
            an.x += a * v.x; an.y += a * v.y; an.z += a * v.z; an.w += a * v.w;
        }
    }
    float ip = g_invdegp[gw], in_ = g_invdegn[gw];
    float4 xp = *(const float4*)(g_proj + (size_t)gw * 512 + 256 + co);
    float4 xn = *(const float4*)(g_proj + (size_t)gw * 512 + 384 + co);
    float4 hp, hn;
    hp.x = ap.x * ip + xp.x; hp.y = ap.y * ip + xp.y;
    hp.z = ap.z * ip + xp.z; hp.w = ap.w * ip + xp.w;
    hn.x = an.x * in_ + xn.x; hn.y = an.y * in_ + xn.y;
    hn.z = an.z * in_ + xn.z; hn.w = an.w * in_ + xn.w;
    if (lrelu) {
        hp.x = hp.x > 0.f ? hp.x : 0.01f * hp.x;
        hp.y = hp.y > 0.f ? hp.y : 0.01f * hp.y;
        hp.z = hp.z > 0.f ? hp.z : 0.01f * hp.z;
        hp.w = hp.w > 0.f ? hp.w : 0.01f * hp.w;
        hn.x = hn.x > 0.f ? hn.x : 0.01f * hn.x;
        hn.y = hn.y > 0.f ? hn.y : 0.01f * hn.y;
        hn.z = hn.z > 0.f ? hn.z : 0.01f * hn.z;
        hn.w = hn.w > 0.f ? hn.w : 0.01f * hn.w;
    }
    *(float4*)(hout + (size_t)gw * 256 + co) = hp;
    *(float4*)(hout + (size_t)gw * 256 + 128 + co) = hn;
}

// ---------------- readout: g[64 x 256] = h1.view(64,51200) @ Wr^T + br ----------------
__global__ void k_ginit(const float* __restrict__ br) {
    g_g[blockIdx.x * HID + threadIdx.x] = br[threadIdx.x];
}

// grid: x = m-tile (8 x 32 cols), y = k-split (25 x 2048)
__global__ void __launch_bounds__(256) k_readout(const float* __restrict__ Wr) {
    __shared__ float As[64][64];
    __shared__ float Bs[64][32];
    const float* __restrict__ A = g_h1;   // [64 x 51200] contiguous view
    int tid = threadIdx.x;
    int m0 = blockIdx.x * 32;
    int kbase = blockIdx.y * 2048;
    int tx = tid & 31;       // m
    int gy = tid >> 5;       // graph group (8 groups of 8)
    float acc[8];
#pragma unroll
    for (int i = 0; i < 8; i++) acc[i] = 0.f;

    for (int k0 = kbase; k0 < kbase + 2048; k0 += 64) {
        {
            int gIdx = tid >> 2;
            int kk = (tid & 3) * 16;
            const float4* s4 = (const float4*)(A + (size_t)gIdx * RDK + k0 + kk);
            float4* d4 = (float4*)&As[gIdx][kk];
            d4[0] = s4[0]; d4[1] = s4[1]; d4[2] = s4[2]; d4[3] = s4[3];
        }
        {
            int mi = tid >> 3;
            int kk = (tid & 7) * 8;
            const float4* s4 = (const float4*)(Wr + (size_t)(m0 + mi) * RDK + k0 + kk);
            float4 v0 = s4[0], v1 = s4[1];
            Bs[kk + 0][mi] = v0.x; Bs[kk + 1][mi] = v0.y;
            Bs[kk + 2][mi] = v0.z; Bs[kk + 3][mi] = v0.w;
            Bs[kk + 4][mi] = v1.x; Bs[kk + 5][mi] = v1.y;
            Bs[kk + 6][mi] = v1.z; Bs[kk + 7][mi] = v1.w;
        }
        __syncthreads();
#pragma unroll 8
        for (int kk = 0; kk < 64; kk++) {
            float b = Bs[kk][tx];
#pragma unroll
            for (int i = 0; i < 8; i++) acc[i] += As[gy * 8 + i][kk] * b;
        }
        __syncthreads();
    }
#pragma unroll
    for (int i = 0; i < 8; i++)
        atomicAdd(&g_g[(gy * 8 + i) * HID + m0 + tx], acc[i]);
}

__global__ void k_final(const float* __restrict__ Wl, const float* __restrict__ bl,
                        float* __restrict__ out) {
    __shared__ float red[256];
    int t = threadIdx.x, b = blockIdx.x;
    red[t] = g_g[b * HID + t] * Wl[t];
    __syncthreads();
    for (int o = 128; o > 0; o >>= 1) {
        if (t < o) red[t] += red[t + o];
        __syncthreads();
    }
    if (t == 0) out[b] = red[0] + bl[0];
}

// ---------------- launch ----------------
extern "C" void kernel_launch(void* const* d_in, const int* in_sizes, int n_in,
                              void* d_out, int out_size) {
    const float* x   = (const float*)d_in[0];
    const int*   ei  = (const int*)d_in[1];
    const float* ew  = (const float*)d_in[2];
    // d_in[3] = batch, unused (layout is contiguous by construction)
    const float* Wp0 = (const float*)d_in[4],  *bp0 = (const float*)d_in[5];
    const float* Wn0 = (const float*)d_in[6],  *bn0 = (const float*)d_in[7];
    const float* Wp1 = (const float*)d_in[8],  *bp1 = (const float*)d_in[9];
    const float* Wn1 = (const float*)d_in[10], *bn1 = (const float*)d_in[11];
    const float* Wp2 = (const float*)d_in[12], *bp2 = (const float*)d_in[13];
    const float* Wn2 = (const float*)d_in[14], *bn2 = (const float*)d_in[15];
    const float* Wr  = (const float*)d_in[16], *br  = (const float*)d_in[17];
    const float* Wl  = (const float*)d_in[18], *bl  = (const float*)d_in[19];
    float* out = (float*)d_out;

    // graph preprocessing (per call; deterministic)
    k_decode<<<NE / 256, 256>>>(ei);
    k_zero_nodes<<<(NN + 255) / 256, 256>>>();
    k_hist<<<NE / 256, 256>>>(ew);
    k_scan<<<1, 1024>>>();
    k_scatter<<<NE / 256, 256>>>(ew);

    // layer 0 (K = 200, input x)
    k_pack<<<(200 * 512 + 255) / 256, 256>>>(Wp0, Wn0, bp0, bn0, 200);
    k_gemm<<<dim3(8, 100), 256>>>(x, 0, 200);
    k_agg<<<NE / 256, 256>>>(1, 1);     // 1600 blocks = 12800 warps

    // layer 1 (K = 256, input h1)
    k_pack<<<(256 * 512 + 255) / 256, 256>>>(Wp1, Wn1, bp1, bn1, 256);
    k_gemm<<<dim3(8, 100), 256>>>(nullptr, 1, 256);
    k_agg<<<NE / 256, 256>>>(2, 1);

    // layer 2 (K = 256, input h2, no lrelu)
    k_pack<<<(256 * 512 + 255) / 256, 256>>>(Wp2, Wn2, bp2, bn2, 256);
    k_gemm<<<dim3(8, 100), 256>>>(nullptr, 2, 256);
    k_agg<<<NE / 256, 256>>>(1, 0);

    // readout + final
    k_ginit<<<NG, 256>>>(br);
    k_readout<<<dim3(8, 25), 256>>>(Wr);
    k_final<<<NG, 256>>>(Wl, bl, out);
}

// round 2
// speedup vs baseline: 1.4633x; 1.4633x over previous
#include <cuda_runtime.h>
#include <cuda_bf16.h>
#include <cstdint>

#define NN 12800          // nodes
#define NE 409600         // edges
#define HID 256
#define NG 64             // graphs
#define RDK 51200         // 200*256 readout K

// ---------------- static device scratch (no allocs allowed) ----------------
__device__ int   g_src[NE];
__device__ int   g_dst[NE];
__device__ int   g_cnt[NN];
__device__ int   g_rowptr[NN + 1];
__device__ int   g_cursor[NN];
__device__ int   g_degp[NN];
__device__ int   g_degn[NN];
__device__ float g_invdegp[NN];
__device__ float g_invdegn[NN];
__device__ int   g_esrc[NE];
__device__ float g_ews[NE];
__device__ int   g_bsum[50];
__device__ float g_h1[NN * HID];
__device__ float g_h2[NN * HID];
__device__ float g_proj[(size_t)NN * 512];
__device__ __nv_bfloat16 g_Bh[512 * 256];   // packed weight hi, [m][k] m-major
__device__ __nv_bfloat16 g_Bl[512 * 256];   // packed weight lo (residual)
__device__ float g_bias[512];
__device__ float g_g[NG * HID];

// ---------------- edge decode: int64 vs int32 probe ----------------
__global__ void k_decode(const int* __restrict__ ei) {
    bool is64 = ((ei[1] | ei[3] | ei[5] | ei[7] | ei[9] | ei[11] | ei[13] | ei[15]) == 0);
    int e = blockIdx.x * blockDim.x + threadIdx.x;
    if (e >= NE) return;
    if (is64) {
        const long long* q = (const long long*)ei;
        g_src[e] = (int)q[e];
        g_dst[e] = (int)q[NE + e];
    } else {
        g_src[e] = ei[e];
        g_dst[e] = ei[NE + e];
    }
}

__global__ void k_zero_nodes() {
    int i = blockIdx.x * blockDim.x + threadIdx.x;
    if (i < NN) { g_cnt[i] = 0; g_degp[i] = 0; g_degn[i] = 0; }
}

__global__ void k_hist(const float* __restrict__ w) {
    int e = blockIdx.x * blockDim.x + threadIdx.x;
    if (e >= NE) return;
    int d = g_dst[e];
    atomicAdd(&g_cnt[d], 1);
    float we = w[e];
    if (we > 0.f)      atomicAdd(&g_degp[d], 1);
    else if (we < 0.f) atomicAdd(&g_degn[d], 1);
}

// ---------------- 3-phase scan over 12800 counts (50 blocks x 256) ----------------
__global__ void k_scan1() {
    __shared__ int ss[256];
    int b = blockIdx.x, t = threadIdx.x;
    int idx = b * 256 + t;
    int v = g_cnt[idx];
    ss[t] = v; __syncthreads();
    for (int off = 1; off < 256; off <<= 1) {
        int u = 0;
        if (t >= off) u = ss[t - off];
        __syncthreads();
        if (t >= off) ss[t] += u;
        __syncthreads();
    }
    g_rowptr[idx] = ss[t] - v;     // local exclusive
    if (t == 255) g_bsum[b] = ss[t];
}

__global__ void k_scan2() {
    if (threadIdx.x == 0) {
        int s = 0;
        for (int i = 0; i < 50; i++) { int c = g_bsum[i]; g_bsum[i] = s; s += c; }
    }
}

__global__ void k_scan3() {
    int b = blockIdx.x, t = threadIdx.x;
    int idx = b * 256 + t;
    int r = g_rowptr[idx] + g_bsum[b];
    g_rowptr[idx] = r;
    g_cursor[idx] = r;
    g_invdegp[idx] = 1.f / fmaxf((float)g_degp[idx], 1.f);
    g_invdegn[idx] = 1.f / fmaxf((float)g_degn[idx], 1.f);
    if (idx == 0) g_rowptr[NN] = NE;
}

__global__ void k_scatter(const float* __restrict__ w) {
    int e = blockIdx.x * blockDim.x + threadIdx.x;
    if (e >= NE) return;
    int d = g_dst[e];
    int pos = atomicAdd(&g_cursor[d], 1);
    g_esrc[pos] = g_src[e];
    g_ews[pos]  = w[e];
}

// ---------------- pack weights -> bf16 hi/lo, m-major [512][256] ----------------
// cols 0..127: Wp agg-part, 128..255: Wn agg-part, 256..383: Wp x-part(+bp), 384..511: Wn x-part(+bn)
__global__ void k_pack(const float* __restrict__ Wp, const float* __restrict__ Wn,
                       const float* __restrict__ bp, const float* __restrict__ bn, int D) {
    int idx = blockIdx.x * blockDim.x + threadIdx.x;
    if (idx >= 512 * 256) return;
    int m = idx >> 8, k = idx & 255;
    int twoD = 2 * D;
    float v = 0.f;
    if (k < D) {
        if (m < 128)       v = Wp[m * twoD + k];
        else if (m < 256)  v = Wn[(m - 128) * twoD + k];
        else if (m < 384)  v = Wp[(m - 256) * twoD + D + k];
        else               v = Wn[(m - 384) * twoD + D + k];
    }
    __nv_bfloat16 h = __float2bfloat16(v);
    g_Bh[idx] = h;
    g_Bl[idx] = __float2bfloat16(v - __bfloat162float(h));
    if (k == 0)
        g_bias[m] = (m < 256) ? 0.f : ((m < 384) ? bp[m - 256] : bn[m - 384]);
}

// ---------------- bf16x3 tensor-core GEMM: proj[NN x 512] = A[NN x K] @ B + bias ----------------
// BM=128, BN=128, BK=32; 8 warps of 64x32 (2 in M, 4 in N); mma.m16n8k16.bf16
__device__ __forceinline__ void mma16816(float* d, const uint32_t* a, const uint32_t* b) {
    asm volatile("mma.sync.aligned.m16n8k16.row.col.f32.bf16.bf16.f32 "
        "{%0,%1,%2,%3},{%4,%5,%6,%7},{%8,%9},{%0,%1,%2,%3};"
        : "+f"(d[0]), "+f"(d[1]), "+f"(d[2]), "+f"(d[3])
        : "r"(a[0]), "r"(a[1]), "r"(a[2]), "r"(a[3]), "r"(b[0]), "r"(b[1]));
}

#define SROW 18   // smem row stride in 32-bit words (36 bf16)

__global__ void __launch_bounds__(256) k_gemm(const float* __restrict__ Ax, int asel,
                                              int K, int ktiles) {
    const float* __restrict__ A = (asel == 0) ? Ax : ((asel == 1) ? g_h1 : g_h2);
    __shared__ __nv_bfloat16 sAh[128][36];
    __shared__ __nv_bfloat16 sAl[128][36];
    __shared__ __nv_bfloat16 sBh[128][36];
    __shared__ __nv_bfloat16 sBl[128][36];

    int tid = threadIdx.x;
    int row0 = blockIdx.y * 128;
    int col0 = blockIdx.x * 128;
    int wid = tid >> 5, lane = tid & 31;
    int wm = wid & 1, wn = wid >> 1;     // 2 warps in M (64 rows), 4 in N (32 cols)
    int g = lane >> 2, c = lane & 3;

    float acc[4][4][4];
#pragma unroll
    for (int mt = 0; mt < 4; mt++)
#pragma unroll
        for (int nt = 0; nt < 4; nt++)
#pragma unroll
            for (int i = 0; i < 4; i++) acc[mt][nt][i] = 0.f;

    int lr = tid & 127;          // load row within tile
    int lh = tid >> 7;           // k-half (0/1): 16 elems each

    for (int kt = 0; kt < ktiles; kt++) {
        int k0 = kt * 32;
        // ---- A: 16 fp32 -> bf16 hi/lo ----
        {
            const float* ap = A + (size_t)(row0 + lr) * K + k0 + lh * 16;
            float av[16];
#pragma unroll
            for (int q = 0; q < 4; q++) {
                float4 v = make_float4(0.f, 0.f, 0.f, 0.f);
                if (k0 + lh * 16 + q * 4 < K) v = *(const float4*)(ap + q * 4);
                av[q*4+0] = v.x; av[q*4+1] = v.y; av[q*4+2] = v.z; av[q*4+3] = v.w;
            }
            __nv_bfloat162* dh = (__nv_bfloat162*)&sAh[lr][lh * 16];
            __nv_bfloat162* dl = (__nv_bfloat162*)&sAl[lr][lh * 16];
#pragma unroll
            for (int q = 0; q < 8; q++) {
                float x0 = av[2*q], x1 = av[2*q+1];
                __nv_bfloat16 h0 = __float2bfloat16(x0);
                __nv_bfloat16 h1 = __float2bfloat16(x1);
                dh[q] = __halves2bfloat162(h0, h1);
                dl[q] = __floats2bfloat162_rn(x0 - __bfloat162float(h0),
                                              x1 - __bfloat162float(h1));
            }
        }
        // ---- B: already split bf16, copy rows ----
        {
            const uint4* sh = (const uint4*)(g_Bh + (size_t)(col0 + lr) * 256 + k0 + lh * 16);
            const uint4* sl = (const uint4*)(g_Bl + (size_t)(col0 + lr) * 256 + k0 + lh * 16);
            uint4 v0 = sh[0], v1 = sh[1];
            uint4 w0 = sl[0], w1 = sl[1];
            uint32_t* dbh = (uint32_t*)&sBh[lr][lh * 16];
            uint32_t* dbl = (uint32_t*)&sBl[lr][lh * 16];
            dbh[0]=v0.x; dbh[1]=v0.y; dbh[2]=v0.z; dbh[3]=v0.w;
            dbh[4]=v1.x; dbh[5]=v1.y; dbh[6]=v1.z; dbh[7]=v1.w;
            dbl[0]=w0.x; dbl[1]=w0.y; dbl[2]=w0.z; dbl[3]=w0.w;
            dbl[4]=w1.x; dbl[5]=w1.y; dbl[6]=w1.z; dbl[7]=w1.w;
        }
        __syncthreads();

#pragma unroll
        for (int ks = 0; ks < 2; ks++) {
            uint32_t ah[4][4], al_[4][4], bh[4][2], bl[4][2];
#pragma unroll
            for (int mt = 0; mt < 4; mt++) {
                int r = wm * 64 + mt * 16 + g;
                const uint32_t* p0 = (const uint32_t*)sAh + r * SROW + ks * 8 + c;
                const uint32_t* p1 = p0 + 8 * SROW;
                ah[mt][0] = p0[0]; ah[mt][1] = p1[0]; ah[mt][2] = p0[4]; ah[mt][3] = p1[4];
                const uint32_t* q0 = (const uint32_t*)sAl + r * SROW + ks * 8 + c;
                const uint32_t* q1 = q0 + 8 * SROW;
                al_[mt][0] = q0[0]; al_[mt][1] = q1[0]; al_[mt][2] = q0[4]; al_[mt][3] = q1[4];
            }
#pragma unroll
            for (int nt = 0; nt < 4; nt++) {
                int n = wn * 32 + nt * 8 + g;
                const uint32_t* p = (const uint32_t*)sBh + n * SROW + ks * 8 + c;
                bh[nt][0] = p[0]; bh[nt][1] = p[4];
                const uint32_t* q = (const uint32_t*)sBl + n * SROW + ks * 8 + c;
                bl[nt][0] = q[0]; bl[nt][1] = q[4];
            }
#pragma unroll
            for (int mt = 0; mt < 4; mt++)
#pragma unroll
                for (int nt = 0; nt < 4; nt++) {
                    mma16816(acc[mt][nt], ah[mt], bh[nt]);
                    mma16816(acc[mt][nt], ah[mt], bl[nt]);
                    mma16816(acc[mt][nt], al_[mt], bh[nt]);
                }
        }
        __syncthreads();
    }

    // ---- store + bias ----
#pragma unroll
    for (int mt = 0; mt < 4; mt++) {
        int row = row0 + wm * 64 + mt * 16 + g;
#pragma unroll
        for (int nt = 0; nt < 4; nt++) {
            int col = col0 + wn * 32 + nt * 8 + 2 * c;
            float2 bb = *(const float2*)&g_bias[col];
            float2 o0, o1;
            o0.x = acc[mt][nt][0] + bb.x; o0.y = acc[mt][nt][1] + bb.y;
            o1.x = acc[mt][nt][2] + bb.x; o1.y = acc[mt][nt][3] + bb.y;
            *(float2*)&g_proj[(size_t)row * 512 + col] = o0;
            *(float2*)&g_proj[(size_t)(row + 8) * 512 + col] = o1;
        }
    }
}

// ---------------- per-node signed mean aggregation + combine (+leaky relu) ----------------
__global__ void k_agg(int outsel, int lrelu) {
    float* __restrict__ hout = (outsel == 1) ? g_h1 : g_h2;
    int gw = (blockIdx.x * blockDim.x + threadIdx.x) >> 5;
    if (gw >= NN) return;
    int lane = threadIdx.x & 31;
    int co = lane * 4;
    int s0 = g_rowptr[gw], s1 = g_rowptr[gw + 1];
    float4 ap = make_float4(0, 0, 0, 0), an = make_float4(0, 0, 0, 0);
    for (int e = s0; e < s1; e++) {
        int s = g_esrc[e];
        float w = g_ews[e];
        if (w > 0.f) {
            float4 v = *(const float4*)(g_proj + (size_t)s * 512 + co);
            ap.x += w * v.x; ap.y += w * v.y; ap.z += w * v.z; ap.w += w * v.w;
        } else {
            float4 v = *(const float4*)(g_proj + (size_t)s * 512 + 128 + co);
            float a = -w;
            an.x += a * v.x; an.y += a * v.y; an.z += a * v.z; an.w += a * v.w;
        }
    }
    float ip = g_invdegp[gw], in_ = g_invdegn[gw];
    float4 xp = *(const float4*)(g_proj + (size_t)gw * 512 + 256 + co);
    float4 xn = *(const float4*)(g_proj + (size_t)gw * 512 + 384 + co);
    float4 hp, hn;
    hp.x = ap.x * ip + xp.x; hp.y = ap.y * ip + xp.y;
    hp.z = ap.z * ip + xp.z; hp.w = ap.w * ip + xp.w;
    hn.x = an.x * in_ + xn.x; hn.y = an.y * in_ + xn.y;
    hn.z = an.z * in_ + xn.z; hn.w = an.w * in_ + xn.w;
    if (lrelu) {
        hp.x = hp.x > 0.f ? hp.x : 0.01f * hp.x;
        hp.y = hp.y > 0.f ? hp.y : 0.01f * hp.y;
        hp.z = hp.z > 0.f ? hp.z : 0.01f * hp.z;
        hp.w = hp.w > 0.f ? hp.w : 0.01f * hp.w;
        hn.x = hn.x > 0.f ? hn.x : 0.01f * hn.x;
        hn.y = hn.y > 0.f ? hn.y : 0.01f * hn.y;
        hn.z = hn.z > 0.f ? hn.z : 0.01f * hn.z;
        hn.w = hn.w > 0.f ? hn.w : 0.01f * hn.w;
    }
    *(float4*)(hout + (size_t)gw * 256 + co) = hp;
    *(float4*)(hout + (size_t)gw * 256 + 128 + co) = hn;
}

// ---------------- readout: g[64 x 256] = h1.view(64,51200) @ Wr^T + br ----------------
__global__ void k_ginit(const float* __restrict__ br) {
    g_g[blockIdx.x * HID + threadIdx.x] = br[threadIdx.x];
}

// grid: x = m-tile (8 x 32 cols), y = k-split (50 x 1024)
__global__ void __launch_bounds__(256) k_readout(const float* __restrict__ Wr) {
    __shared__ float As[64][64];
    __shared__ float Bs[64][32];
    const float* __restrict__ A = g_h1;   // [64 x 51200] contiguous view
    int tid = threadIdx.x;
    int m0 = blockIdx.x * 32;
    int kbase = blockIdx.y * 1024;
    int tx = tid & 31;       // m
    int gy = tid >> 5;       // graph group (8 groups of 8)
    float acc[8];
#pragma unroll
    for (int i = 0; i < 8; i++) acc[i] = 0.f;

    for (int k0 = kbase; k0 < kbase + 1024; k0 += 64) {
        {
            int gIdx = tid >> 2;
            int kk = (tid & 3) * 16;
            const float4* s4 = (const float4*)(A + (size_t)gIdx * RDK + k0 + kk);
            float4* d4 = (float4*)&As[gIdx][kk];
            d4[0] = s4[0]; d4[1] = s4[1]; d4[2] = s4[2]; d4[3] = s4[3];
        }
        {
            int mi = tid >> 3;
            int kk = (tid & 7) * 8;
            const float4* s4 = (const float4*)(Wr + (size_t)(m0 + mi) * RDK + k0 + kk);
            float4 v0 = s4[0], v1 = s4[1];
            Bs[kk + 0][mi] = v0.x; Bs[kk + 1][mi] = v0.y;
            Bs[kk + 2][mi] = v0.z; Bs[kk + 3][mi] = v0.w;
            Bs[kk + 4][mi] = v1.x; Bs[kk + 5][mi] = v1.y;
            Bs[kk + 6][mi] = v1.z; Bs[kk + 7][mi] = v1.w;
        }
        __syncthreads();
#pragma unroll 8
        for (int kk = 0; kk < 64; kk++) {
            float b = Bs[kk][tx];
#pragma unroll
            for (int i = 0; i < 8; i++) acc[i] += As[gy * 8 + i][kk] * b;
        }
        __syncthreads();
    }
#pragma unroll
    for (int i = 0; i < 8; i++)
        atomicAdd(&g_g[(gy * 8 + i) * HID + m0 + tx], acc[i]);
}

__global__ void k_final(const float* __restrict__ Wl, const float* __restrict__ bl,
                        float* __restrict__ out) {
    __shared__ float red[256];
    int t = threadIdx.x, b = blockIdx.x;
    red[t] = g_g[b * HID + t] * Wl[t];
    __syncthreads();
    for (int o = 128; o > 0; o >>= 1) {
        if (t < o) red[t] += red[t + o];
        __syncthreads();
    }
    if (t == 0) out[b] = red[0] + bl[0];
}

// ---------------- launch ----------------
extern "C" void kernel_launch(void* const* d_in, const int* in_sizes, int n_in,
                              void* d_out, int out_size) {
    const float* x   = (const float*)d_in[0];
    const int*   ei  = (const int*)d_in[1];
    const float* ew  = (const float*)d_in[2];
    const float* Wp0 = (const float*)d_in[4],  *bp0 = (const float*)d_in[5];
    const float* Wn0 = (const float*)d_in[6],  *bn0 = (const float*)d_in[7];
    const float* Wp1 = (const float*)d_in[8],  *bp1 = (const float*)d_in[9];
    const float* Wn1 = (const float*)d_in[10], *bn1 = (const float*)d_in[11];
    const float* Wp2 = (const float*)d_in[12], *bp2 = (const float*)d_in[13];
    const float* Wn2 = (const float*)d_in[14], *bn2 = (const float*)d_in[15];
    const float* Wr  = (const float*)d_in[16], *br  = (const float*)d_in[17];
    const float* Wl  = (const float*)d_in[18], *bl  = (const float*)d_in[19];
    float* out = (float*)d_out;

    // graph preprocessing
    k_decode<<<NE / 256, 256>>>(ei);
    k_zero_nodes<<<(NN + 255) / 256, 256>>>();
    k_hist<<<NE / 256, 256>>>(ew);
    k_scan1<<<50, 256>>>();
    k_scan2<<<1, 32>>>();
    k_scan3<<<50, 256>>>();
    k_scatter<<<NE / 256, 256>>>(ew);

    // layer 0 (K = 200, 7 k-tiles)
    k_pack<<<(512 * 256) / 256, 256>>>(Wp0, Wn0, bp0, bn0, 200);
    k_gemm<<<dim3(4, 100), 256>>>(x, 0, 200, 7);
    k_agg<<<NE / 256, 256>>>(1, 1);

    // layer 1 (K = 256, 8 k-tiles)
    k_pack<<<(512 * 256) / 256, 256>>>(Wp1, Wn1, bp1, bn1, 256);
    k_gemm<<<dim3(4, 100), 256>>>(nullptr, 1, 256, 8);
    k_agg<<<NE / 256, 256>>>(2, 1);

    // layer 2 (K = 256, no lrelu)
    k_pack<<<(512 * 256) / 256, 256>>>(Wp2, Wn2, bp2, bn2, 256);
    k_gemm<<<dim3(4, 100), 256>>>(nullptr, 2, 256, 8);
    k_agg<<<NE / 256, 256>>>(1, 0);

    // readout + final
    k_ginit<<<NG, 256>>>(br);
    k_readout<<<dim3(8, 50), 256>>>(Wr);
    k_final<<<NG, 256>>>(Wl, bl, out);
}

// round 4
// speedup vs baseline: 1.9041x; 1.3012x over previous
#include <cuda_runtime.h>
#include <cuda_bf16.h>
#include <cstdint>

#define NN 12800
#define NE 409600
#define HID 256
#define NG 64
#define RDK 51200

// ---------------- static device scratch ----------------
__device__ int   g_src[NE];
__device__ int   g_dst[NE];
__device__ int   g_cnt[NN];
__device__ int   g_rowptr[NN + 1];
__device__ int   g_cursor[NN];
__device__ int   g_degp[NN];
__device__ int   g_degn[NN];
__device__ float g_invdegp[NN];
__device__ float g_invdegn[NN];
__device__ int   g_esrc[NE];
__device__ float g_ews[NE];
__device__ int   g_bsum[50];
__device__ float g_proj[(size_t)NN * 512];
__device__ __nv_bfloat16 g_Ah[(size_t)NN * 256];   // activation hi ([64][51200] view for readout)
__device__ __nv_bfloat16 g_Al[(size_t)NN * 256];   // activation lo
__device__ __nv_bfloat16 g_Bh[512 * 256];          // packed weight hi, [n][k]
__device__ __nv_bfloat16 g_Bl[512 * 256];
__device__ float g_bias[512];
__device__ float g_g[NG * HID];

// ---------------- preprocessing ----------------
__global__ void k_decode(const int* __restrict__ ei) {
    bool is64 = ((ei[1] | ei[3] | ei[5] | ei[7] | ei[9] | ei[11] | ei[13] | ei[15]) == 0);
    int e = blockIdx.x * blockDim.x + threadIdx.x;
    if (e >= NE) return;
    if (is64) {
        const long long* q = (const long long*)ei;
        g_src[e] = (int)q[e]; g_dst[e] = (int)q[NE + e];
    } else {
        g_src[e] = ei[e]; g_dst[e] = ei[NE + e];
    }
}
__global__ void k_zero_nodes() {
    int i = blockIdx.x * blockDim.x + threadIdx.x;
    if (i < NN) { g_cnt[i] = 0; g_degp[i] = 0; g_degn[i] = 0; }
}
__global__ void k_hist(const float* __restrict__ w) {
    int e = blockIdx.x * blockDim.x + threadIdx.x;
    if (e >= NE) return;
    int d = g_dst[e];
    atomicAdd(&g_cnt[d], 1);
    float we = w[e];
    if (we > 0.f)      atomicAdd(&g_degp[d], 1);
    else if (we < 0.f) atomicAdd(&g_degn[d], 1);
}
__global__ void k_scan1() {
    __shared__ int ss[256];
    int b = blockIdx.x, t = threadIdx.x;
    int idx = b * 256 + t;
    int v = g_cnt[idx];
    ss[t] = v; __syncthreads();
    for (int off = 1; off < 256; off <<= 1) {
        int u = 0;
        if (t >= off) u = ss[t - off];
        __syncthreads();
        if (t >= off) ss[t] += u;
        __syncthreads();
    }
    g_rowptr[idx] = ss[t] - v;
    if (t == 255) g_bsum[b] = ss[t];
}
__global__ void k_scan2() {
    if (threadIdx.x == 0) {
        int s = 0;
        for (int i = 0; i < 50; i++) { int c = g_bsum[i]; g_bsum[i] = s; s += c; }
    }
}
__global__ void k_scan3() {
    int b = blockIdx.x, t = threadIdx.x;
    int idx = b * 256 + t;
    int r = g_rowptr[idx] + g_bsum[b];
    g_rowptr[idx] = r; g_cursor[idx] = r;
    g_invdegp[idx] = 1.f / fmaxf((float)g_degp[idx], 1.f);
    g_invdegn[idx] = 1.f / fmaxf((float)g_degn[idx], 1.f);
    if (idx == 0) g_rowptr[NN] = NE;
}
__global__ void k_scatter(const float* __restrict__ w) {
    int e = blockIdx.x * blockDim.x + threadIdx.x;
    if (e >= NE) return;
    int d = g_dst[e];
    int pos = atomicAdd(&g_cursor[d], 1);
    g_esrc[pos] = g_src[e];
    g_ews[pos]  = w[e];
}

// ---------------- split x into bf16 hi/lo (layer-0 A), zero-pad K to 256 ----------------
__global__ void k_splitx(const float* __restrict__ x) {
    int idx = blockIdx.x * 256 + threadIdx.x;
    int r = idx >> 8, c = idx & 255;
    float v = (c < 200) ? x[r * 200 + c] : 0.f;
    __nv_bfloat16 h = __float2bfloat16(v);
    g_Ah[idx] = h;
    g_Al[idx] = __float2bfloat16(v - __bfloat162float(h));
}

// ---------------- pack weights -> bf16 hi/lo, [n=512][k=256] ----------------
__global__ void k_pack(const float* __restrict__ Wp, const float* __restrict__ Wn,
                       const float* __restrict__ bp, const float* __restrict__ bn, int D) {
    int idx = blockIdx.x * blockDim.x + threadIdx.x;
    if (idx >= 512 * 256) return;
    int m = idx >> 8, k = idx & 255;
    int twoD = 2 * D;
    float v = 0.f;
    if (k < D) {
        if (m < 128)       v = Wp[m * twoD + k];
        else if (m < 256)  v = Wn[(m - 128) * twoD + k];
        else if (m < 384)  v = Wp[(m - 256) * twoD + D + k];
        else               v = Wn[(m - 384) * twoD + D + k];
    }
    __nv_bfloat16 h = __float2bfloat16(v);
    g_Bh[idx] = h;
    g_Bl[idx] = __float2bfloat16(v - __bfloat162float(h));
    if (k == 0)
        g_bias[m] = (m < 256) ? 0.f : ((m < 384) ? bp[m - 256] : bn[m - 384]);
}

// ---------------- mma helpers ----------------
__device__ __forceinline__ void mma16816(float* d, const uint32_t* a, const uint32_t* b) {
    asm volatile("mma.sync.aligned.m16n8k16.row.col.f32.bf16.bf16.f32 "
        "{%0,%1,%2,%3},{%4,%5,%6,%7},{%8,%9},{%0,%1,%2,%3};"
        : "+f"(d[0]), "+f"(d[1]), "+f"(d[2]), "+f"(d[3])
        : "r"(a[0]), "r"(a[1]), "r"(a[2]), "r"(a[3]), "r"(b[0]), "r"(b[1]));
}
__device__ __forceinline__ uint32_t smem_u32(const void* p) {
    uint32_t a;
    asm("{ .reg .u64 t; cvta.to.shared.u64 t, %1; cvt.u32.u64 %0, t; }" : "=r"(a) : "l"(p));
    return a;
}
#define LDSM4(r, a) \
    asm volatile("ldmatrix.sync.aligned.m8n8.x4.shared.b16 {%0,%1,%2,%3}, [%4];" \
        : "=r"((r)[0]), "=r"((r)[1]), "=r"((r)[2]), "=r"((r)[3]) : "r"(a))

// ---------------- GEMM: proj[NN x 512] = A[NN x 256] @ B^T + bias (bf16x3, ldmatrix) ----------------
// grid (4, 100): BM=128, BN=128; 8 warps: wm in {0,1} (64 rows), wn in {0..3} (32 cols)
#define PADH 40   // smem halves per row (80B: conflict-free LDSM phases)

__global__ void __launch_bounds__(256) k_gemm(int ktiles) {
    __shared__ __align__(16) __nv_bfloat16 sAh[128][PADH];
    __shared__ __align__(16) __nv_bfloat16 sAl[128][PADH];
    __shared__ __align__(16) __nv_bfloat16 sBh[128][PADH];
    __shared__ __align__(16) __nv_bfloat16 sBl[128][PADH];

    int tid = threadIdx.x;
    int wid = tid >> 5, lane = tid & 31;
    int wm = wid & 1, wn = wid >> 1;
    int row0 = blockIdx.y * 128;
    int col0 = blockIdx.x * 128;
    int g = lane >> 2, c = lane & 3;

    float acc[4][4][4];
#pragma unroll
    for (int mt = 0; mt < 4; mt++)
#pragma unroll
        for (int nt = 0; nt < 4; nt++)
#pragma unroll
            for (int i = 0; i < 4; i++) acc[mt][nt][i] = 0.f;

    // ldmatrix lane addressing (A): lanes 0-15 -> rows, lanes 16-31 -> rows @ k+8
    int lrow = lane & 15;
    int lk = (lane >> 4) * 8;
    // B addressing: lane group g8 -> (nt within pair, k-half)
    int g8 = lane >> 3;
    int b_nt = g8 >> 1;          // 0/1 within the pair
    int b_kh = (g8 & 1) * 8;
    int b_row = lane & 7;

    for (int kt = 0; kt < ktiles; kt++) {
        int k0 = kt * 32;
        // stage tiles: each array 128 rows x 32 halves = 512 uint4; 2 per thread
#pragma unroll
        for (int i = 0; i < 2; i++) {
            int idx = tid + i * 256;
            int r = idx >> 2, v = (idx & 3) * 8;
            *(uint4*)&sAh[r][v] = *(const uint4*)(g_Ah + (size_t)(row0 + r) * 256 + k0 + v);
            *(uint4*)&sAl[r][v] = *(const uint4*)(g_Al + (size_t)(row0 + r) * 256 + k0 + v);
            *(uint4*)&sBh[r][v] = *(const uint4*)(g_Bh + (size_t)(col0 + r) * 256 + k0 + v);
            *(uint4*)&sBl[r][v] = *(const uint4*)(g_Bl + (size_t)(col0 + r) * 256 + k0 + v);
        }
        __syncthreads();

#pragma unroll
        for (int ks = 0; ks < 2; ks++) {
            uint32_t ah[4][4], al_[4][4], bh[4][2], bl[4][2];
#pragma unroll
            for (int mt = 0; mt < 4; mt++) {
                int r = wm * 64 + mt * 16 + lrow;
                LDSM4(ah[mt], smem_u32(&sAh[r][ks * 16 + lk]));
                LDSM4(al_[mt], smem_u32(&sAl[r][ks * 16 + lk]));
            }
#pragma unroll
            for (int np = 0; np < 2; np++) {
                int n = wn * 32 + (np * 2 + b_nt) * 8 + b_row;
                uint32_t r4[4];
                LDSM4(r4, smem_u32(&sBh[n][ks * 16 + b_kh]));
                bh[np*2][0] = r4[0]; bh[np*2][1] = r4[1];
                bh[np*2+1][0] = r4[2]; bh[np*2+1][1] = r4[3];
                LDSM4(r4, smem_u32(&sBl[n][ks * 16 + b_kh]));
                bl[np*2][0] = r4[0]; bl[np*2][1] = r4[1];
                bl[np*2+1][0] = r4[2]; bl[np*2+1][1] = r4[3];
            }
#pragma unroll
            for (int mt = 0; mt < 4; mt++)
#pragma unroll
                for (int nt = 0; nt < 4; nt++) {
                    mma16816(acc[mt][nt], ah[mt], bh[nt]);
                    mma16816(acc[mt][nt], ah[mt], bl[nt]);
                    mma16816(acc[mt][nt], al_[mt], bh[nt]);
                }
        }
        __syncthreads();
    }

    // store + bias
#pragma unroll
    for (int mt = 0; mt < 4; mt++) {
        int row = row0 + wm * 64 + mt * 16 + g;
#pragma unroll
        for (int nt = 0; nt < 4; nt++) {
            int col = col0 + wn * 32 + nt * 8 + 2 * c;
            float2 bb = *(const float2*)&g_bias[col];
            float2 o0, o1;
            o0.x = acc[mt][nt][0] + bb.x; o0.y = acc[mt][nt][1] + bb.y;
            o1.x = acc[mt][nt][2] + bb.x; o1.y = acc[mt][nt][3] + bb.y;
            *(float2*)&g_proj[(size_t)row * 512 + col] = o0;
            *(float2*)&g_proj[(size_t)(row + 8) * 512 + col] = o1;
        }
    }
}

// ---------------- aggregation: signed mean + combine (+lrelu) -> split bf16 out ----------------
__global__ void k_agg(int lrelu) {
    int gw = (blockIdx.x * blockDim.x + threadIdx.x) >> 5;
    if (gw >= NN) return;
    int lane = threadIdx.x & 31;
    int co = lane * 4;
    int s0 = g_rowptr[gw], s1 = g_rowptr[gw + 1];
    float4 ap = make_float4(0, 0, 0, 0), an = make_float4(0, 0, 0, 0);
    for (int e = s0; e < s1; e++) {
        int s = g_esrc[e];
        float w = g_ews[e];
        if (w > 0.f) {
            float4 v = *(const float4*)(g_proj + (size_t)s * 512 + co);
            ap.x += w * v.x; ap.y += w * v.y; ap.z += w * v.z; ap.w += w * v.w;
        } else {
            float4 v = *(const float4*)(g_proj + (size_t)s * 512 + 128 + co);
            float a = -w;
            an.x += a * v.x; an.y += a * v.y; an.z += a * v.z; an.w += a * v.w;
        }
    }
    float ip = g_invdegp[gw], in_ = g_invdegn[gw];
    float4 xp = *(const float4*)(g_proj + (size_t)gw * 512 + 256 + co);
    float4 xn = *(const float4*)(g_proj + (size_t)gw * 512 + 384 + co);
    float hv[8];
    hv[0] = ap.x * ip + xp.x; hv[1] = ap.y * ip + xp.y;
    hv[2] = ap.z * ip + xp.z; hv[3] = ap.w * ip + xp.w;
    hv[4] = an.x * in_ + xn.x; hv[5] = an.y * in_ + xn.y;
    hv[6] = an.z * in_ + xn.z; hv[7] = an.w * in_ + xn.w;
    if (lrelu) {
#pragma unroll
        for (int i = 0; i < 8; i++) hv[i] = hv[i] > 0.f ? hv[i] : 0.01f * hv[i];
    }
    __nv_bfloat16 hh[8], hl[8];
#pragma unroll
    for (int i = 0; i < 8; i++) {
        hh[i] = __float2bfloat16(hv[i]);
        hl[i] = __float2bfloat16(hv[i] - __bfloat162float(hh[i]));
    }
    size_t base = (size_t)gw * 256;
    *(uint2*)(g_Ah + base + co)       = *(uint2*)&hh[0];
    *(uint2*)(g_Ah + base + 128 + co) = *(uint2*)&hh[4];
    *(uint2*)(g_Al + base + co)       = *(uint2*)&hl[0];
    *(uint2*)(g_Al + base + 128 + co) = *(uint2*)&hl[4];
}

// ---------------- readout: g[64 x 256] += h.view(64,51200) @ Wr^T  (bf16x3 mma.sync) ----------------
__global__ void k_ginit(const float* __restrict__ br) {
    g_g[blockIdx.x * HID + threadIdx.x] = br[threadIdx.x];
}

#define SROW 18

// grid (2, 50): n-tile 128, k-chunk 1024
__global__ void __launch_bounds__(256) k_readout(const float* __restrict__ Wr) {
    __shared__ __nv_bfloat16 sAh[64][36], sAl[64][36];
    __shared__ __nv_bfloat16 sBh[128][36], sBl[128][36];
    int tid = threadIdx.x;
    int wid = tid >> 5, lane = tid & 31;
    int wm = wid & 3, wn = wid >> 2;
    int g = lane >> 2, c = lane & 3;
    int n0 = blockIdx.x * 128;
    int kbase = blockIdx.y * 1024;

    float acc[8][4];
#pragma unroll
    for (int nt = 0; nt < 8; nt++)
#pragma unroll
        for (int i = 0; i < 4; i++) acc[nt][i] = 0.f;

    for (int kt = 0; kt < 32; kt++) {
        int k0 = kbase + kt * 32;
        {   // A: 64 rows x 32 k, hi/lo already bf16
            int r = tid >> 2, v = tid & 3;
            uint4 h = *(const uint4*)(g_Ah + (size_t)r * RDK + k0 + v * 8);
            uint4 l = *(const uint4*)(g_Al + (size_t)r * RDK + k0 + v * 8);
            uint32_t* dh = (uint32_t*)sAh + r * SROW + v * 4;
            uint32_t* dl = (uint32_t*)sAl + r * SROW + v * 4;
            dh[0] = h.x; dh[1] = h.y; dh[2] = h.z; dh[3] = h.w;
            dl[0] = l.x; dl[1] = l.y; dl[2] = l.z; dl[3] = l.w;
        }
        // B: Wr fp32 128 rows x 32 k -> split
#pragma unroll
        for (int i = 0; i < 4; i++) {
            int idx = tid + i * 256;
            int r = idx >> 3, v = idx & 7;
            float4 w = *(const float4*)(Wr + (size_t)(n0 + r) * RDK + k0 + v * 4);
            __nv_bfloat16 h0 = __float2bfloat16(w.x), h1 = __float2bfloat16(w.y);
            __nv_bfloat16 h2 = __float2bfloat16(w.z), h3 = __float2bfloat16(w.w);
            uint32_t* dh = (uint32_t*)sBh + r * SROW + v * 2;
            uint32_t* dl = (uint32_t*)sBl + r * SROW + v * 2;
            __nv_bfloat162 p0 = __halves2bfloat162(h0, h1);
            __nv_bfloat162 p1 = __halves2bfloat162(h2, h3);
            dh[0] = *(uint32_t*)&p0; dh[1] = *(uint32_t*)&p1;
            __nv_bfloat162 q0 = __floats2bfloat162_rn(w.x - __bfloat162float(h0), w.y - __bfloat162float(h1));
            __nv_bfloat162 q1 = __floats2bfloat162_rn(w.z - __bfloat162float(h2), w.w - __bfloat162float(h3));
            dl[0] = *(uint32_t*)&q0; dl[1] = *(uint32_t*)&q1;
        }
        __syncthreads();
#pragma unroll
        for (int ks = 0; ks < 2; ks++) {
            uint32_t ah[4], al_[4], bh[8][2], bl[8][2];
            {
                int r = wm * 16 + g;
                const uint32_t* p0 = (const uint32_t*)sAh + r * SROW + ks * 8 + c;
                const uint32_t* p1 = p0 + 8 * SROW;
                ah[0] = p0[0]; ah[1] = p1[0]; ah[2] = p0[4]; ah[3] = p1[4];
                const uint32_t* q0 = (const uint32_t*)sAl + r * SROW + ks * 8 + c;
                const uint32_t* q1 = q0 + 8 * SROW;
                al_[0] = q0[0]; al_[1] = q1[0]; al_[2] = q0[4]; al_[3] = q1[4];
            }
#pragma unroll
            for (int nt = 0; nt < 8; nt++) {
                int n = wn * 64 + nt * 8 + g;
                const uint32_t* p = (const uint32_t*)sBh + n * SROW + ks * 8 + c;
                bh[nt][0] = p[0]; bh[nt][1] = p[4];
                const uint32_t* q = (const uint32_t*)sBl + n * SROW + ks * 8 + c;
                bl[nt][0] = q[0]; bl[nt][1] = q[4];
            }
#pragma unroll
            for (int nt = 0; nt < 8; nt++) {
                mma16816(acc[nt], ah, bh[nt]);
                mma16816(acc[nt], ah, bl[nt]);
                mma16816(acc[nt], al_, bh[nt]);
            }
        }
        __syncthreads();
    }
    int m = wm * 16 + g;
#pragma unroll
    for (int nt = 0; nt < 8; nt++) {
        int n = n0 + wn * 64 + nt * 8 + c * 2;
        atomicAdd(&g_g[m * 256 + n],           acc[nt][0]);
        atomicAdd(&g_g[m * 256 + n + 1],       acc[nt][1]);
        atomicAdd(&g_g[(m + 8) * 256 + n],     acc[nt][2]);
        atomicAdd(&g_g[(m + 8) * 256 + n + 1], acc[nt][3]);
    }
}

__global__ void k_final(const float* __restrict__ Wl, const float* __restrict__ bl,
                        float* __restrict__ out) {
    __shared__ float red[256];
    int t = threadIdx.x, b = blockIdx.x;
    red[t] = g_g[b * HID + t] * Wl[t];
    __syncthreads();
    for (int o = 128; o > 0; o >>= 1) {
        if (t < o) red[t] += red[t + o];
        __syncthreads();
    }
    if (t == 0) out[b] = red[0] + bl[0];
}

// ---------------- launch ----------------
extern "C" void kernel_launch(void* const* d_in, const int* in_sizes, int n_in,
                              void* d_out, int out_size) {
    const float* x   = (const float*)d_in[0];
    const int*   ei  = (const int*)d_in[1];
    const float* ew  = (const float*)d_in[2];
    const float* Wp0 = (const float*)d_in[4],  *bp0 = (const float*)d_in[5];
    const float* Wn0 = (const float*)d_in[6],  *bn0 = (const float*)d_in[7];
    const float* Wp1 = (const float*)d_in[8],  *bp1 = (const float*)d_in[9];
    const float* Wn1 = (const float*)d_in[10], *bn1 = (const float*)d_in[11];
    const float* Wp2 = (const float*)d_in[12], *bp2 = (const float*)d_in[13];
    const float* Wn2 = (const float*)d_in[14], *bn2 = (const float*)d_in[15];
    const float* Wr  = (const float*)d_in[16], *br  = (const float*)d_in[17];
    const float* Wl  = (const float*)d_in[18], *bl  = (const float*)d_in[19];
    float* out = (float*)d_out;

    // graph preprocessing
    k_decode<<<NE / 256, 256>>>(ei);
    k_zero_nodes<<<(NN + 255) / 256, 256>>>();
    k_hist<<<NE / 256, 256>>>(ew);
    k_scan1<<<50, 256>>>();
    k_scan2<<<1, 32>>>();
    k_scan3<<<50, 256>>>();
    k_scatter<<<NE / 256, 256>>>(ew);

    // layer 0 (K=200 padded to 256; tiles beyond k=224 are all-zero -> 7 tiles)
    k_splitx<<<NN, 256>>>(x);
    k_pack<<<512, 256>>>(Wp0, Wn0, bp0, bn0, 200);
    k_gemm<<<dim3(4, 100), 256>>>(7);
    k_agg<<<1600, 256>>>(1);

    // layer 1
    k_pack<<<512, 256>>>(Wp1, Wn1, bp1, bn1, 256);
    k_gemm<<<dim3(4, 100), 256>>>(8);
    k_agg<<<1600, 256>>>(1);

    // layer 2
    k_pack<<<512, 256>>>(Wp2, Wn2, bp2, bn2, 256);
    k_gemm<<<dim3(4, 100), 256>>>(8);
    k_agg<<<1600, 256>>>(0);

    // readout + final
    k_ginit<<<NG, 256>>>(br);
    k_readout<<<dim3(2, 50), 256>>>(Wr);
    k_final<<<NG, 256>>>(Wl, bl, out);
}

// round 5
// speedup vs baseline: 2.0700x; 1.0871x over previous
#include <cuda_runtime.h>
#include <cuda_bf16.h>
#include <cstdint>

#define NN 12800
#define NE 409600
#define HID 256
#define NG 64
#define RDK 51200

// ---------------- static device scratch ----------------
__device__ int   g_src[NE];
__device__ int   g_dst[NE];
__device__ int   g_cnt[NN];
__device__ int   g_rowptr[NN + 1];
__device__ int   g_cursor[NN];
__device__ int   g_degp[NN];
__device__ int   g_degn[NN];
__device__ float g_invdegp[NN];
__device__ float g_invdegn[NN];
__device__ int   g_esrc[NE];
__device__ float g_ews[NE];
__device__ int   g_bsum[50];
__device__ float g_proj[(size_t)NN * 512];
__device__ __nv_bfloat16 g_Ah[(size_t)NN * 256];   // activation hi ([64][51200] view for readout)
__device__ __nv_bfloat16 g_Al[(size_t)NN * 256];   // activation lo
__device__ __nv_bfloat16 g_Bh[512 * 256];          // packed weight hi, [n][k]
__device__ __nv_bfloat16 g_Bl[512 * 256];
__device__ float g_bias[512];
__device__ float g_g[NG * HID];

// ---------------- helpers ----------------
__device__ __forceinline__ uint32_t smem_u32(const void* p) {
    uint32_t a;
    asm("{ .reg .u64 t; cvta.to.shared.u64 t, %1; cvt.u32.u64 %0, t; }" : "=r"(a) : "l"(p));
    return a;
}
__device__ __forceinline__ void cpasync16(uint32_t dst, const void* src) {
    asm volatile("cp.async.cg.shared.global [%0], [%1], 16;" :: "r"(dst), "l"(src));
}
#define CP_COMMIT() asm volatile("cp.async.commit_group;" ::: "memory")
#define CP_WAIT(n)  asm volatile("cp.async.wait_group %0;" :: "n"(n) : "memory")
__device__ __forceinline__ void mma16816(float* d, const uint32_t* a, const uint32_t* b) {
    asm volatile("mma.sync.aligned.m16n8k16.row.col.f32.bf16.bf16.f32 "
        "{%0,%1,%2,%3},{%4,%5,%6,%7},{%8,%9},{%0,%1,%2,%3};"
        : "+f"(d[0]), "+f"(d[1]), "+f"(d[2]), "+f"(d[3])
        : "r"(a[0]), "r"(a[1]), "r"(a[2]), "r"(a[3]), "r"(b[0]), "r"(b[1]));
}
#define LDSM4(r, a) \
    asm volatile("ldmatrix.sync.aligned.m8n8.x4.shared.b16 {%0,%1,%2,%3}, [%4];" \
        : "=r"((r)[0]), "=r"((r)[1]), "=r"((r)[2]), "=r"((r)[3]) : "r"(a))

// ---------------- preprocessing ----------------
__global__ void k_zero_nodes() {
    int i = blockIdx.x * blockDim.x + threadIdx.x;
    if (i < NN) { g_cnt[i] = 0; g_degp[i] = 0; g_degn[i] = 0; }
}
__global__ void k_decode_hist(const int* __restrict__ ei, const float* __restrict__ w) {
    bool is64 = ((ei[1] | ei[3] | ei[5] | ei[7] | ei[9] | ei[11] | ei[13] | ei[15]) == 0);
    int e = blockIdx.x * blockDim.x + threadIdx.x;
    if (e >= NE) return;
    int s, d;
    if (is64) {
        const long long* q = (const long long*)ei;
        s = (int)q[e]; d = (int)q[NE + e];
    } else {
        s = ei[e]; d = ei[NE + e];
    }
    g_src[e] = s; g_dst[e] = d;
    atomicAdd(&g_cnt[d], 1);
    float we = w[e];
    if (we > 0.f)      atomicAdd(&g_degp[d], 1);
    else if (we < 0.f) atomicAdd(&g_degn[d], 1);
}
__global__ void k_scan1() {
    __shared__ int ss[256];
    int b = blockIdx.x, t = threadIdx.x;
    int idx = b * 256 + t;
    int v = g_cnt[idx];
    ss[t] = v; __syncthreads();
    for (int off = 1; off < 256; off <<= 1) {
        int u = 0;
        if (t >= off) u = ss[t - off];
        __syncthreads();
        if (t >= off) ss[t] += u;
        __syncthreads();
    }
    g_rowptr[idx] = ss[t] - v;
    if (t == 255) g_bsum[b] = ss[t];
}
__global__ void k_scan2() {
    if (threadIdx.x == 0) {
        int s = 0;
        for (int i = 0; i < 50; i++) { int c = g_bsum[i]; g_bsum[i] = s; s += c; }
    }
}
__global__ void k_scan3() {
    int b = blockIdx.x, t = threadIdx.x;
    int idx = b * 256 + t;
    int r = g_rowptr[idx] + g_bsum[b];
    g_rowptr[idx] = r; g_cursor[idx] = r;
    g_invdegp[idx] = 1.f / fmaxf((float)g_degp[idx], 1.f);
    g_invdegn[idx] = 1.f / fmaxf((float)g_degn[idx], 1.f);
    if (idx == 0) g_rowptr[NN] = NE;
}
__global__ void k_scatter(const float* __restrict__ w) {
    int e = blockIdx.x * blockDim.x + threadIdx.x;
    if (e >= NE) return;
    int d = g_dst[e];
    int pos = atomicAdd(&g_cursor[d], 1);
    g_esrc[pos] = g_src[e];
    g_ews[pos]  = w[e];
}

// ---------------- split x into bf16 hi/lo (layer-0 A), zero-pad K to 256 ----------------
__global__ void k_splitx(const float* __restrict__ x) {
    int idx = blockIdx.x * 256 + threadIdx.x;
    int r = idx >> 8, c = idx & 255;
    float v = (c < 200) ? x[r * 200 + c] : 0.f;
    __nv_bfloat16 h = __float2bfloat16(v);
    g_Ah[idx] = h;
    g_Al[idx] = __float2bfloat16(v - __bfloat162float(h));
}

// ---------------- pack weights -> bf16 hi/lo, [n=512][k=256] ----------------
__global__ void k_pack(const float* __restrict__ Wp, const float* __restrict__ Wn,
                       const float* __restrict__ bp, const float* __restrict__ bn, int D) {
    int idx = blockIdx.x * blockDim.x + threadIdx.x;
    if (idx >= 512 * 256) return;
    int m = idx >> 8, k = idx & 255;
    int twoD = 2 * D;
    float v = 0.f;
    if (k < D) {
        if (m < 128)       v = Wp[m * twoD + k];
        else if (m < 256)  v = Wn[(m - 128) * twoD + k];
        else if (m < 384)  v = Wp[(m - 256) * twoD + D + k];
        else               v = Wn[(m - 384) * twoD + D + k];
    }
    __nv_bfloat16 h = __float2bfloat16(v);
    g_Bh[idx] = h;
    g_Bl[idx] = __float2bfloat16(v - __bfloat162float(h));
    if (k == 0)
        g_bias[m] = (m < 256) ? 0.f : ((m < 384) ? bp[m - 256] : bn[m - 384]);
}

// ---------------- GEMM: proj[NN x 512] = A @ B^T + bias (bf16x3, cp.async 2-stage) ----------------
// grid (4, 100): BM=128, BN=128; 8 warps: wm in {0,1}, wn in {0..3}
#define PADH 40                          // halves per smem row (80B, conflict-free LDSM)
#define ARRH (128 * PADH)                // halves per array
#define STGH (4 * ARRH)                  // halves per stage

__global__ void __launch_bounds__(256) k_gemm(int ktiles) {
    extern __shared__ __align__(16) __nv_bfloat16 sm[];

    int tid = threadIdx.x;
    int wid = tid >> 5, lane = tid & 31;
    int wm = wid & 1, wn = wid >> 1;
    int row0 = blockIdx.y * 128;
    int col0 = blockIdx.x * 128;
    int g = lane >> 2, c = lane & 3;

    float acc[4][4][4];
#pragma unroll
    for (int mt = 0; mt < 4; mt++)
#pragma unroll
        for (int nt = 0; nt < 4; nt++)
#pragma unroll
            for (int i = 0; i < 4; i++) acc[mt][nt][i] = 0.f;

    // ldmatrix addressing
    int lrow = lane & 15;
    int lk = (lane >> 4) * 8;
    int g8 = lane >> 3;
    int b_nt = g8 >> 1;
    int b_kh = (g8 & 1) * 8;
    int b_row = lane & 7;

    // cp.async mapping: per array 2 chunks/thread: r=idx>>2, v=(idx&3)*8
    int r0 = tid >> 2, v0 = (tid & 3) * 8;
    int r1 = (tid + 256) >> 2, v1 = ((tid + 256) & 3) * 8;
    uint32_t smbase = smem_u32(sm);

    auto load_stage = [&](int kt, int s) {
        int k0 = kt * 32;
        uint32_t sb = smbase + (uint32_t)s * (STGH * 2);
        cpasync16(sb + 0 * ARRH * 2 + (r0 * PADH + v0) * 2, g_Ah + (size_t)(row0 + r0) * 256 + k0 + v0);
        cpasync16(sb + 0 * ARRH * 2 + (r1 * PADH + v1) * 2, g_Ah + (size_t)(row0 + r1) * 256 + k0 + v1);
        cpasync16(sb + 1 * ARRH * 2 + (r0 * PADH + v0) * 2, g_Al + (size_t)(row0 + r0) * 256 + k0 + v0);
        cpasync16(sb + 1 * ARRH * 2 + (r1 * PADH + v1) * 2, g_Al + (size_t)(row0 + r1) * 256 + k0 + v1);
        cpasync16(sb + 2 * ARRH * 2 + (r0 * PADH + v0) * 2, g_Bh + (size_t)(col0 + r0) * 256 + k0 + v0);
        cpasync16(sb + 2 * ARRH * 2 + (r1 * PADH + v1) * 2, g_Bh + (size_t)(col0 + r1) * 256 + k0 + v1);
        cpasync16(sb + 3 * ARRH * 2 + (r0 * PADH + v0) * 2, g_Bl + (size_t)(col0 + r0) * 256 + k0 + v0);
        cpasync16(sb + 3 * ARRH * 2 + (r1 * PADH + v1) * 2, g_Bl + (size_t)(col0 + r1) * 256 + k0 + v1);
        CP_COMMIT();
    };

    load_stage(0, 0);

    for (int kt = 0; kt < ktiles; kt++) {
        int s = kt & 1;
        bool more = (kt + 1 < ktiles);
        if (more) load_stage(kt + 1, s ^ 1);
        if (more) { CP_WAIT(1); } else { CP_WAIT(0); }
        __syncthreads();

        const __nv_bfloat16* sAh = sm + s * STGH;
        const __nv_bfloat16* sAl = sAh + ARRH;
        const __nv_bfloat16* sBh = sAl + ARRH;
        const __nv_bfloat16* sBl = sBh + ARRH;

#pragma unroll
        for (int ks = 0; ks < 2; ks++) {
            uint32_t ah[4][4], al_[4][4], bh[4][2], bl[4][2];
#pragma unroll
            for (int mt = 0; mt < 4; mt++) {
                int r = wm * 64 + mt * 16 + lrow;
                LDSM4(ah[mt], smem_u32(sAh + r * PADH + ks * 16 + lk));
                LDSM4(al_[mt], smem_u32(sAl + r * PADH + ks * 16 + lk));
            }
#pragma unroll
            for (int np = 0; np < 2; np++) {
                int n = wn * 32 + (np * 2 + b_nt) * 8 + b_row;
                uint32_t r4[4];
                LDSM4(r4, smem_u32(sBh + n * PADH + ks * 16 + b_kh));
                bh[np*2][0] = r4[0]; bh[np*2][1] = r4[1];
                bh[np*2+1][0] = r4[2]; bh[np*2+1][1] = r4[3];
                LDSM4(r4, smem_u32(sBl + n * PADH + ks * 16 + b_kh));
                bl[np*2][0] = r4[0]; bl[np*2][1] = r4[1];
                bl[np*2+1][0] = r4[2]; bl[np*2+1][1] = r4[3];
            }
#pragma unroll
            for (int mt = 0; mt < 4; mt++)
#pragma unroll
                for (int nt = 0; nt < 4; nt++) {
                    mma16816(acc[mt][nt], ah[mt], bh[nt]);
                    mma16816(acc[mt][nt], ah[mt], bl[nt]);
                    mma16816(acc[mt][nt], al_[mt], bh[nt]);
                }
        }
        __syncthreads();
    }

    // store + bias
#pragma unroll
    for (int mt = 0; mt < 4; mt++) {
        int row = row0 + wm * 64 + mt * 16 + g;
#pragma unroll
        for (int nt = 0; nt < 4; nt++) {
            int col = col0 + wn * 32 + nt * 8 + 2 * c;
            float2 bb = *(const float2*)&g_bias[col];
            float2 o0, o1;
            o0.x = acc[mt][nt][0] + bb.x; o0.y = acc[mt][nt][1] + bb.y;
            o1.x = acc[mt][nt][2] + bb.x; o1.y = acc[mt][nt][3] + bb.y;
            *(float2*)&g_proj[(size_t)row * 512 + col] = o0;
            *(float2*)&g_proj[(size_t)(row + 8) * 512 + col] = o1;
        }
    }
}

// ---------------- aggregation: signed mean + combine (+lrelu) -> split bf16 out ----------------
__global__ void k_agg(int lrelu) {
    int gw = (blockIdx.x * blockDim.x + threadIdx.x) >> 5;
    if (gw >= NN) return;
    int lane = threadIdx.x & 31;
    int co = lane * 4;
    int s0 = g_rowptr[gw], s1 = g_rowptr[gw + 1];
    float4 ap = make_float4(0, 0, 0, 0), an = make_float4(0, 0, 0, 0);
    int e = s0;
    for (; e + 2 <= s1; e += 2) {
        int sa = g_esrc[e],     sb = g_esrc[e + 1];
        float wa = g_ews[e],    wb = g_ews[e + 1];
        const float* pa = g_proj + (size_t)sa * 512 + (wa > 0.f ? 0 : 128) + co;
        const float* pb = g_proj + (size_t)sb * 512 + (wb > 0.f ? 0 : 128) + co;
        float4 va = *(const float4*)pa;
        float4 vb = *(const float4*)pb;
        float aa = fabsf(wa), ab = fabsf(wb);
        if (wa > 0.f) {
            ap.x += aa * va.x; ap.y += aa * va.y; ap.z += aa * va.z; ap.w += aa * va.w;
        } else {
            an.x += aa * va.x; an.y += aa * va.y; an.z += aa * va.z; an.w += aa * va.w;
        }
        if (wb > 0.f) {
            ap.x += ab * vb.x; ap.y += ab * vb.y; ap.z += ab * vb.z; ap.w += ab * vb.w;
        } else {
            an.x += ab * vb.x; an.y += ab * vb.y; an.z += ab * vb.z; an.w += ab * vb.w;
        }
    }
    if (e < s1) {
        int sa = g_esrc[e];
        float wa = g_ews[e];
        const float* pa = g_proj + (size_t)sa * 512 + (wa > 0.f ? 0 : 128) + co;
        float4 va = *(const float4*)pa;
        float aa = fabsf(wa);
        if (wa > 0.f) {
            ap.x += aa * va.x; ap.y += aa * va.y; ap.z += aa * va.z; ap.w += aa * va.w;
        } else {
            an.x += aa * va.x; an.y += aa * va.y; an.z += aa * va.z; an.w += aa * va.w;
        }
    }
    float ip = g_invdegp[gw], in_ = g_invdegn[gw];
    float4 xp = *(const float4*)(g_proj + (size_t)gw * 512 + 256 + co);
    float4 xn = *(const float4*)(g_proj + (size_t)gw * 512 + 384 + co);
    float hv[8];
    hv[0] = ap.x * ip + xp.x; hv[1] = ap.y * ip + xp.y;
    hv[2] = ap.z * ip + xp.z; hv[3] = ap.w * ip + xp.w;
    hv[4] = an.x * in_ + xn.x; hv[5] = an.y * in_ + xn.y;
    hv[6] = an.z * in_ + xn.z; hv[7] = an.w * in_ + xn.w;
    if (lrelu) {
#pragma unroll
        for (int i = 0; i < 8; i++) hv[i] = hv[i] > 0.f ? hv[i] : 0.01f * hv[i];
    }
    __nv_bfloat16 hh[8], hl[8];
#pragma unroll
    for (int i = 0; i < 8; i++) {
        hh[i] = __float2bfloat16(hv[i]);
        hl[i] = __float2bfloat16(hv[i] - __bfloat162float(hh[i]));
    }
    size_t base = (size_t)gw * 256;
    *(uint2*)(g_Ah + base + co)       = *(uint2*)&hh[0];
    *(uint2*)(g_Ah + base + 128 + co) = *(uint2*)&hh[4];
    *(uint2*)(g_Al + base + co)       = *(uint2*)&hl[0];
    *(uint2*)(g_Al + base + 128 + co) = *(uint2*)&hl[4];
}

// ---------------- readout: g[64 x 256] += h.view(64,51200) @ Wr^T  (bf16x3 mma.sync) ----------------
__global__ void k_ginit(const float* __restrict__ br) {
    g_g[blockIdx.x * HID + threadIdx.x] = br[threadIdx.x];
}

#define SROW 18

// grid (2, 50): n-tile 128, k-chunk 1024
__global__ void __launch_bounds__(256) k_readout(const float* __restrict__ Wr) {
    __shared__ __nv_bfloat16 sAh[64][36], sAl[64][36];
    __shared__ __nv_bfloat16 sBh[128][36], sBl[128][36];
    int tid = threadIdx.x;
    int wid = tid >> 5, lane = tid & 31;
    int wm = wid & 3, wn = wid >> 2;
    int g = lane >> 2, c = lane & 3;
    int n0 = blockIdx.x * 128;
    int kbase = blockIdx.y * 1024;

    float acc[8][4];
#pragma unroll
    for (int nt = 0; nt < 8; nt++)
#pragma unroll
        for (int i = 0; i < 4; i++) acc[nt][i] = 0.f;

    for (int kt = 0; kt < 32; kt++) {
        int k0 = kbase + kt * 32;
        {
            int r = tid >> 2, v = tid & 3;
            uint4 h = *(const uint4*)(g_Ah + (size_t)r * RDK + k0 + v * 8);
            uint4 l = *(const uint4*)(g_Al + (size_t)r * RDK + k0 + v * 8);
            uint32_t* dh = (uint32_t*)sAh + r * SROW + v * 4;
            uint32_t* dl = (uint32_t*)sAl + r * SROW + v * 4;
            dh[0] = h.x; dh[1] = h.y; dh[2] = h.z; dh[3] = h.w;
            dl[0] = l.x; dl[1] = l.y; dl[2] = l.z; dl[3] = l.w;
        }
#pragma unroll
        for (int i = 0; i < 4; i++) {
            int idx = tid + i * 256;
            int r = idx >> 3, v = idx & 7;
            float4 w = *(const float4*)(Wr + (size_t)(n0 + r) * RDK + k0 + v * 4);
            __nv_bfloat16 h0 = __float2bfloat16(w.x), h1 = __float2bfloat16(w.y);
            __nv_bfloat16 h2 = __float2bfloat16(w.z), h3 = __float2bfloat16(w.w);
            uint32_t* dh = (uint32_t*)sBh + r * SROW + v * 2;
            uint32_t* dl = (uint32_t*)sBl + r * SROW + v * 2;
            __nv_bfloat162 p0 = __halves2bfloat162(h0, h1);
            __nv_bfloat162 p1 = __halves2bfloat162(h2, h3);
            dh[0] = *(uint32_t*)&p0; dh[1] = *(uint32_t*)&p1;
            __nv_bfloat162 q0 = __floats2bfloat162_rn(w.x - __bfloat162float(h0), w.y - __bfloat162float(h1));
            __nv_bfloat162 q1 = __floats2bfloat162_rn(w.z - __bfloat162float(h2), w.w - __bfloat162float(h3));
            dl[0] = *(uint32_t*)&q0; dl[1] = *(uint32_t*)&q1;
        }
        __syncthreads();
#pragma unroll
        for (int ks = 0; ks < 2; ks++) {
            uint32_t ah[4], al_[4], bh[8][2], bl[8][2];
            {
                int r = wm * 16 + g;
                const uint32_t* p0 = (const uint32_t*)sAh + r * SROW + ks * 8 + c;
                const uint32_t* p1 = p0 + 8 * SROW;
                ah[0] = p0[0]; ah[1] = p1[0]; ah[2] = p0[4]; ah[3] = p1[4];
                const uint32_t* q0 = (const uint32_t*)sAl + r * SROW + ks * 8 + c;
                const uint32_t* q1 = q0 + 8 * SROW;
                al_[0] = q0[0]; al_[1] = q1[0]; al_[2] = q0[4]; al_[3] = q1[4];
            }
#pragma unroll
            for (int nt = 0; nt < 8; nt++) {
                int n = wn * 64 + nt * 8 + g;
                const uint32_t* p = (const uint32_t*)sBh + n * SROW + ks * 8 + c;
                bh[nt][0] = p[0]; bh[nt][1] = p[4];
                const uint32_t* q = (const uint32_t*)sBl + n * SROW + ks * 8 + c;
                bl[nt][0] = q[0]; bl[nt][1] = q[4];
            }
#pragma unroll
            for (int nt = 0; nt < 8; nt++) {
                mma16816(acc[nt], ah, bh[nt]);
                mma16816(acc[nt], ah, bl[nt]);
                mma16816(acc[nt], al_, bh[nt]);
            }
        }
        __syncthreads();
    }
    int m = wm * 16 + g;
#pragma unroll
    for (int nt = 0; nt < 8; nt++) {
        int n = n0 + wn * 64 + nt * 8 + c * 2;
        atomicAdd(&g_g[m * 256 + n],           acc[nt][0]);
        atomicAdd(&g_g[m * 256 + n + 1],       acc[nt][1]);
        atomicAdd(&g_g[(m + 8) * 256 + n],     acc[nt][2]);
        atomicAdd(&g_g[(m + 8) * 256 + n + 1], acc[nt][3]);
    }
}

__global__ void k_final(const float* __restrict__ Wl, const float* __restrict__ bl,
                        float* __restrict__ out) {
    __shared__ float red[256];
    int t = threadIdx.x, b = blockIdx.x;
    red[t] = g_g[b * HID + t] * Wl[t];
    __syncthreads();
    for (int o = 128; o > 0; o >>= 1) {
        if (t < o) red[t] += red[t + o];
        __syncthreads();
    }
    if (t == 0) out[b] = red[0] + bl[0];
}

// ---------------- launch ----------------
extern "C" void kernel_launch(void* const* d_in, const int* in_sizes, int n_in,
                              void* d_out, int out_size) {
    const float* x   = (const float*)d_in[0];
    const int*   ei  = (const int*)d_in[1];
    const float* ew  = (const float*)d_in[2];
    const float* Wp0 = (const float*)d_in[4],  *bp0 = (const float*)d_in[5];
    const float* Wn0 = (const float*)d_in[6],  *bn0 = (const float*)d_in[7];
    const float* Wp1 = (const float*)d_in[8],  *bp1 = (const float*)d_in[9];
    const float* Wn1 = (const float*)d_in[10], *bn1 = (const float*)d_in[11];
    const float* Wp2 = (const float*)d_in[12], *bp2 = (const float*)d_in[13];
    const float* Wn2 = (const float*)d_in[14], *bn2 = (const float*)d_in[15];
    const float* Wr  = (const float*)d_in[16], *br  = (const float*)d_in[17];
    const float* Wl  = (const float*)d_in[18], *bl  = (const float*)d_in[19];
    float* out = (float*)d_out;

    const int GEMM_SMEM = 2 * STGH * 2;   // 2 stages * halves * 2B = 81920
    cudaFuncSetAttribute(k_gemm, cudaFuncAttributeMaxDynamicSharedMemorySize, GEMM_SMEM);

    // layer-0 GEMM placed 4th so ncu's capture slot profiles it
    k_splitx<<<NN, 256>>>(x);
    k_pack<<<512, 256>>>(Wp0, Wn0, bp0, bn0, 200);
    k_zero_nodes<<<(NN + 255) / 256, 256>>>();
    k_gemm<<<dim3(4, 100), 256, GEMM_SMEM>>>(7);

    // graph preprocessing (needed only by k_agg)
    k_decode_hist<<<NE / 256, 256>>>(ei, ew);
    k_scan1<<<50, 256>>>();
    k_scan2<<<1, 32>>>();
    k_scan3<<<50, 256>>>();
    k_scatter<<<NE / 256, 256>>>(ew);

    k_agg<<<1600, 256>>>(1);

    // layer 1
    k_pack<<<512, 256>>>(Wp1, Wn1, bp1, bn1, 256);
    k_gemm<<<dim3(4, 100), 256, GEMM_SMEM>>>(8);
    k_agg<<<1600, 256>>>(1);

    // layer 2
    k_pack<<<512, 256>>>(Wp2, Wn2, bp2, bn2, 256);
    k_gemm<<<dim3(4, 100), 256, GEMM_SMEM>>>(8);
    k_agg<<<1600, 256>>>(0);

    // readout + final
    k_ginit<<<NG, 256>>>(br);
    k_readout<<<dim3(2, 50), 256>>>(Wr);
    k_final<<<NG, 256>>>(Wl, bl, out);
}

// round 7
// speedup vs baseline: 2.2651x; 1.0943x over previous
#include <cuda_runtime.h>
#include <cuda_bf16.h>
#include <cstdint>

#define NN 12800
#define NE 409600
#define HID 256
#define NG 64
#define RDK 51200

// ---------------- static device scratch ----------------
__device__ int   g_src[NE];
__device__ int   g_dst[NE];
__device__ unsigned long long g_cnt64[NN];   // packed: total | pos<<21 | neg<<42
__device__ int   g_rowptr[NN + 1];
__device__ int   g_cursor[NN];
__device__ float g_invdegp[NN];
__device__ float g_invdegn[NN];
__device__ int   g_esrc[NE];
__device__ float g_ews[NE];
__device__ int   g_bsum[50];
__device__ float g_proj[(size_t)NN * 512];
__device__ __nv_bfloat16 g_Ah[(size_t)NN * 256];
__device__ __nv_bfloat16 g_Al[(size_t)NN * 256];
__device__ __nv_bfloat16 g_Bh[512 * 256];
__device__ __nv_bfloat16 g_Bl[512 * 256];
__device__ float g_bias[512];
__device__ float g_g[NG * HID];

// ---------------- helpers ----------------
__device__ __forceinline__ uint32_t smem_u32(const void* p) {
    uint32_t a;
    asm("{ .reg .u64 t; cvta.to.shared.u64 t, %1; cvt.u32.u64 %0, t; }" : "=r"(a) : "l"(p));
    return a;
}
__device__ __forceinline__ void cpasync16(uint32_t dst, const void* src) {
    asm volatile("cp.async.cg.shared.global [%0], [%1], 16;" :: "r"(dst), "l"(src));
}
#define CP_COMMIT() asm volatile("cp.async.commit_group;" ::: "memory")
#define CP_WAIT(n)  asm volatile("cp.async.wait_group %0;" :: "n"(n) : "memory")
__device__ __forceinline__ void mma16816(float* d, const uint32_t* a, const uint32_t* b) {
    asm volatile("mma.sync.aligned.m16n8k16.row.col.f32.bf16.bf16.f32 "
        "{%0,%1,%2,%3},{%4,%5,%6,%7},{%8,%9},{%0,%1,%2,%3};"
        : "+f"(d[0]), "+f"(d[1]), "+f"(d[2]), "+f"(d[3])
        : "r"(a[0]), "r"(a[1]), "r"(a[2]), "r"(a[3]), "r"(b[0]), "r"(b[1]));
}
#define LDSM4(r, a) \
    asm volatile("ldmatrix.sync.aligned.m8n8.x4.shared.b16 {%0,%1,%2,%3}, [%4];" \
        : "=r"((r)[0]), "=r"((r)[1]), "=r"((r)[2]), "=r"((r)[3]) : "r"(a))

// ---------------- preprocessing ----------------
__global__ void k_zero_nodes() {
    int i = blockIdx.x * blockDim.x + threadIdx.x;
    if (i < NN) g_cnt64[i] = 0ULL;
}
__global__ void k_decode_hist(const int* __restrict__ ei, const float* __restrict__ w) {
    bool is64 = ((ei[1] | ei[3] | ei[5] | ei[7] | ei[9] | ei[11] | ei[13] | ei[15]) == 0);
    int e = blockIdx.x * blockDim.x + threadIdx.x;
    if (e >= NE) return;
    int s, d;
    if (is64) {
        const long long* q = (const long long*)ei;
        s = (int)q[e]; d = (int)q[NE + e];
    } else {
        s = ei[e]; d = ei[NE + e];
    }
    g_src[e] = s; g_dst[e] = d;
    float we = w[e];
    unsigned long long add = 1ULL;
    if (we > 0.f)      add |= (1ULL << 21);
    else if (we < 0.f) add |= (1ULL << 42);
    atomicAdd(&g_cnt64[d], add);
}
__global__ void k_scan1() {
    __shared__ int ss[256];
    int b = blockIdx.x, t = threadIdx.x;
    int idx = b * 256 + t;
    int v = (int)(g_cnt64[idx] & 0x1FFFFFULL);
    ss[t] = v; __syncthreads();
    for (int off = 1; off < 256; off <<= 1) {
        int u = 0;
        if (t >= off) u = ss[t - off];
        __syncthreads();
        if (t >= off) ss[t] += u;
        __syncthreads();
    }
    g_rowptr[idx] = ss[t] - v;
    if (t == 255) g_bsum[b] = ss[t];
}
__global__ void k_scan2() {
    if (threadIdx.x == 0) {
        int s = 0;
        for (int i = 0; i < 50; i++) { int c = g_bsum[i]; g_bsum[i] = s; s += c; }
    }
}
__global__ void k_scan3() {
    int b = blockIdx.x, t = threadIdx.x;
    int idx = b * 256 + t;
    int r = g_rowptr[idx] + g_bsum[b];
    g_rowptr[idx] = r; g_cursor[idx] = r;
    unsigned long long c = g_cnt64[idx];
    int dp = (int)((c >> 21) & 0x1FFFFFULL);
    int dn = (int)(c >> 42);
    g_invdegp[idx] = 1.f / fmaxf((float)dp, 1.f);
    g_invdegn[idx] = 1.f / fmaxf((float)dn, 1.f);
    if (idx == 0) g_rowptr[NN] = NE;
}
__global__ void k_scatter(const float* __restrict__ w) {
    int e = blockIdx.x * blockDim.x + threadIdx.x;
    if (e >= NE) return;
    int d = g_dst[e];
    int pos = atomicAdd(&g_cursor[d], 1);
    g_esrc[pos] = g_src[e];
    g_ews[pos]  = w[e];
}

// ---------------- split x into bf16 hi/lo (layer-0 A), zero-pad K to 256 ----------------
__global__ void k_splitx(const float* __restrict__ x) {
    int idx = blockIdx.x * 256 + threadIdx.x;
    int r = idx >> 8, c = idx & 255;
    float v = (c < 200) ? x[r * 200 + c] : 0.f;
    __nv_bfloat16 h = __float2bfloat16(v);
    g_Ah[idx] = h;
    g_Al[idx] = __float2bfloat16(v - __bfloat162float(h));
}

// ---------------- pack weights -> bf16 hi/lo, [n=512][k=256] ----------------
__global__ void k_pack(const float* __restrict__ Wp, const float* __restrict__ Wn,
                       const float* __restrict__ bp, const float* __restrict__ bn, int D) {
    int idx = blockIdx.x * blockDim.x + threadIdx.x;
    if (idx >= 512 * 256) return;
    int m = idx >> 8, k = idx & 255;
    int twoD = 2 * D;
    float v = 0.f;
    if (k < D) {
        if (m < 128)       v = Wp[m * twoD + k];
        else if (m < 256)  v = Wn[(m - 128) * twoD + k];
        else if (m < 384)  v = Wp[(m - 256) * twoD + D + k];
        else               v = Wn[(m - 384) * twoD + D + k];
    }
    __nv_bfloat16 h = __float2bfloat16(v);
    g_Bh[idx] = h;
    g_Bl[idx] = __float2bfloat16(v - __bfloat162float(h));
    if (k == 0)
        g_bias[m] = (m < 256) ? 0.f : ((m < 384) ? bp[m - 256] : bn[m - 384]);
}

// ---------------- GEMM: proj = A @ B^T + bias (bf16x3, cp.async 2-stage) ----------------
// grid (8, 100): BM=128, BN=64; 8 warps: wm in {0..3} (32 rows), wn in {0,1} (32 cols)
#define PADH 40                          // 80B rows: cp.async-16B aligned + conflict-free LDSM
#define A_H (128 * PADH)
#define B_H (64 * PADH)
#define STGH (2 * A_H + 2 * B_H)        // 15360 halves = 30720 B per stage

__global__ void __launch_bounds__(256, 3) k_gemm(int ktiles) {
    extern __shared__ __align__(16) __nv_bfloat16 sm[];

    int tid = threadIdx.x;
    int wid = tid >> 5, lane = tid & 31;
    int wm = wid & 3, wn = wid >> 2;
    int row0 = blockIdx.y * 128;
    int col0 = blockIdx.x * 64;
    int g = lane >> 2, c = lane & 3;

    float acc[2][4][4];
#pragma unroll
    for (int mt = 0; mt < 2; mt++)
#pragma unroll
        for (int nt = 0; nt < 4; nt++)
#pragma unroll
            for (int i = 0; i < 4; i++) acc[mt][nt][i] = 0.f;

    int lrow = lane & 15;
    int lk = (lane >> 4) * 8;
    int g8 = lane >> 3;
    int b_nt = g8 >> 1;
    int b_kh = (g8 & 1) * 8;
    int b_row = lane & 7;

    int ar = tid >> 2, av = (tid & 3) * 8;
    uint32_t smbase = smem_u32(sm);

    auto load_stage = [&](int kt, int s) {
        int k0 = kt * 32;
        uint32_t sb = smbase + (uint32_t)s * (STGH * 2);
        cpasync16(sb + (ar * PADH + av) * 2,              g_Ah + (size_t)(row0 + ar) * 256 + k0 + av);
        cpasync16(sb + ((ar + 64) * PADH + av) * 2,       g_Ah + (size_t)(row0 + ar + 64) * 256 + k0 + av);
        cpasync16(sb + (A_H + ar * PADH + av) * 2,        g_Al + (size_t)(row0 + ar) * 256 + k0 + av);
        cpasync16(sb + (A_H + (ar + 64) * PADH + av) * 2, g_Al + (size_t)(row0 + ar + 64) * 256 + k0 + av);
        cpasync16(sb + (2 * A_H + ar * PADH + av) * 2,        g_Bh + (size_t)(col0 + ar) * 256 + k0 + av);
        cpasync16(sb + (2 * A_H + B_H + ar * PADH + av) * 2,  g_Bl + (size_t)(col0 + ar) * 256 + k0 + av);
        CP_COMMIT();
    };

    load_stage(0, 0);

    for (int kt = 0; kt < ktiles; kt++) {
        int s = kt & 1;
        bool more = (kt + 1 < ktiles);
        if (more) load_stage(kt + 1, s ^ 1);
        if (more) { CP_WAIT(1); } else { CP_WAIT(0); }
        __syncthreads();

        const __nv_bfloat16* sAh = sm + s * STGH;
        const __nv_bfloat16* sAl = sAh + A_H;
        const __nv_bfloat16* sBh = sAl + A_H;
        const __nv_bfloat16* sBl = sBh + B_H;

#pragma unroll
        for (int ks = 0; ks < 2; ks++) {
            uint32_t ah[2][4], al_[2][4], bh[4][2], bl[4][2];
#pragma unroll
            for (int mt = 0; mt < 2; mt++) {
                int r = wm * 32 + mt * 16 + lrow;
                LDSM4(ah[mt], smem_u32(sAh + r * PADH + ks * 16 + lk));
                LDSM4(al_[mt], smem_u32(sAl + r * PADH + ks * 16 + lk));
            }
#pragma unroll
            for (int np = 0; np < 2; np++) {
                int n = wn * 32 + (np * 2 + b_nt) * 8 + b_row;
                uint32_t r4[4];
                LDSM4(r4, smem_u32(sBh + n * PADH + ks * 16 + b_kh));
                bh[np*2][0] = r4[0]; bh[np*2][1] = r4[1];
                bh[np*2+1][0] = r4[2]; bh[np*2+1][1] = r4[3];
                LDSM4(r4, smem_u32(sBl + n * PADH + ks * 16 + b_kh));
                bl[np*2][0] = r4[0]; bl[np*2][1] = r4[1];
                bl[np*2+1][0] = r4[2]; bl[np*2+1][1] = r4[3];
            }
#pragma unroll
            for (int mt = 0; mt < 2; mt++)
#pragma unroll
                for (int nt = 0; nt < 4; nt++) {
                    mma16816(acc[mt][nt], ah[mt], bh[nt]);
                    mma16816(acc[mt][nt], ah[mt], bl[nt]);
                    mma16816(acc[mt][nt], al_[mt], bh[nt]);
                }
        }
        __syncthreads();
    }

    // store + bias
#pragma unroll
    for (int mt = 0; mt < 2; mt++) {
        int row = row0 + wm * 32 + mt * 16 + g;
#pragma unroll
        for (int nt = 0; nt < 4; nt++) {
            int col = col0 + wn * 32 + nt * 8 + 2 * c;
            float2 bb = *(const float2*)&g_bias[col];
            float2 o0, o1;
            o0.x = acc[mt][nt][0] + bb.x; o0.y = acc[mt][nt][1] + bb.y;
            o1.x = acc[mt][nt][2] + bb.x; o1.y = acc[mt][nt][3] + bb.y;
            *(float2*)&g_proj[(size_t)row * 512 + col] = o0;
            *(float2*)&g_proj[(size_t)(row + 8) * 512 + col] = o1;
        }
    }
}

// ---------------- aggregation ----------------
__global__ void k_agg(int lrelu) {
    int gw = (blockIdx.x * blockDim.x + threadIdx.x) >> 5;
    if (gw >= NN) return;
    int lane = threadIdx.x & 31;
    int co = lane * 4;
    int s0 = g_rowptr[gw], s1 = g_rowptr[gw + 1];
    float4 ap = make_float4(0, 0, 0, 0), an = make_float4(0, 0, 0, 0);
    int e = s0;
    for (; e + 2 <= s1; e += 2) {
        int sa = g_esrc[e],     sb = g_esrc[e + 1];
        float wa = g_ews[e],    wb = g_ews[e + 1];
        const float* pa = g_proj + (size_t)sa * 512 + (wa > 0.f ? 0 : 128) + co;
        const float* pb = g_proj + (size_t)sb * 512 + (wb > 0.f ? 0 : 128) + co;
        float4 va = *(const float4*)pa;
        float4 vb = *(const float4*)pb;
        float aa = fabsf(wa), ab = fabsf(wb);
        if (wa > 0.f) {
            ap.x += aa * va.x; ap.y += aa * va.y; ap.z += aa * va.z; ap.w += aa * va.w;
        } else {
            an.x += aa * va.x; an.y += aa * va.y; an.z += aa * va.z; an.w += aa * va.w;
        }
        if (wb > 0.f) {
            ap.x += ab * vb.x; ap.y += ab * vb.y; ap.z += ab * vb.z; ap.w += ab * vb.w;
        } else {
            an.x += ab * vb.x; an.y += ab * vb.y; an.z += ab * vb.z; an.w += ab * vb.w;
        }
    }
    if (e < s1) {
        int sa = g_esrc[e];
        float wa = g_ews[e];
        const float* pa = g_proj + (size_t)sa * 512 + (wa > 0.f ? 0 : 128) + co;
        float4 va = *(const float4*)pa;
        float aa = fabsf(wa);
        if (wa > 0.f) {
            ap.x += aa * va.x; ap.y += aa * va.y; ap.z += aa * va.z; ap.w += aa * va.w;
        } else {
            an.x += aa * va.x; an.y += aa * va.y; an.z += aa * va.z; an.w += aa * va.w;
        }
    }
    float ip = g_invdegp[gw], in_ = g_invdegn[gw];
    float4 xp = *(const float4*)(g_proj + (size_t)gw * 512 + 256 + co);
    float4 xn = *(const float4*)(g_proj + (size_t)gw * 512 + 384 + co);
    float hv[8];
    hv[0] = ap.x * ip + xp.x; hv[1] = ap.y * ip + xp.y;
    hv[2] = ap.z * ip + xp.z; hv[3] = ap.w * ip + xp.w;
    hv[4] = an.x * in_ + xn.x; hv[5] = an.y * in_ + xn.y;
    hv[6] = an.z * in_ + xn.z; hv[7] = an.w * in_ + xn.w;
    if (lrelu) {
#pragma unroll
        for (int i = 0; i < 8; i++) hv[i] = hv[i] > 0.f ? hv[i] : 0.01f * hv[i];
    }
    __nv_bfloat16 hh[8], hl[8];
#pragma unroll
    for (int i = 0; i < 8; i++) {
        hh[i] = __float2bfloat16(hv[i]);
        hl[i] = __float2bfloat16(hv[i] - __bfloat162float(hh[i]));
    }
    size_t base = (size_t)gw * 256;
    *(uint2*)(g_Ah + base + co)       = *(uint2*)&hh[0];
    *(uint2*)(g_Ah + base + 128 + co) = *(uint2*)&hh[4];
    *(uint2*)(g_Al + base + co)       = *(uint2*)&hl[0];
    *(uint2*)(g_Al + base + 128 + co) = *(uint2*)&hl[4];
}

// ---------------- readout ----------------
__global__ void k_ginit(const float* __restrict__ br) {
    g_g[blockIdx.x * HID + threadIdx.x] = br[threadIdx.x];
}

#define SROW 18

// grid (2, 100): n-tile 128, k-chunk 512
__global__ void __launch_bounds__(256) k_readout(const float* __restrict__ Wr) {
    __shared__ __nv_bfloat16 sAh[64][36], sAl[64][36];
    __shared__ __nv_bfloat16 sBh[128][36], sBl[128][36];
    int tid = threadIdx.x;
    int wid = tid >> 5, lane = tid & 31;
    int wm = wid & 3, wn = wid >> 2;
    int g = lane >> 2, c = lane & 3;
    int n0 = blockIdx.x * 128;
    int kbase = blockIdx.y * 512;

    float acc[8][4];
#pragma unroll
    for (int nt = 0; nt < 8; nt++)
#pragma unroll
        for (int i = 0; i < 4; i++) acc[nt][i] = 0.f;

    for (int kt = 0; kt < 16; kt++) {
        int k0 = kbase + kt * 32;
        {
            int r = tid >> 2, v = tid & 3;
            uint4 h = *(const uint4*)(g_Ah + (size_t)r * RDK + k0 + v * 8);
            uint4 l = *(const uint4*)(g_Al + (size_t)r * RDK + k0 + v * 8);
            uint32_t* dh = (uint32_t*)sAh + r * SROW + v * 4;
            uint32_t* dl = (uint32_t*)sAl + r * SROW + v * 4;
            dh[0] = h.x; dh[1] = h.y; dh[2] = h.z; dh[3] = h.w;
            dl[0] = l.x; dl[1] = l.y; dl[2] = l.z; dl[3] = l.w;
        }
#pragma unroll
        for (int i = 0; i < 4; i++) {
            int idx = tid + i * 256;
            int r = idx >> 3, v = idx & 7;
            float4 w = *(const float4*)(Wr + (size_t)(n0 + r) * RDK + k0 + v * 4);
            __nv_bfloat16 h0 = __float2bfloat16(w.x), h1 = __float2bfloat16(w.y);
            __nv_bfloat16 h2 = __float2bfloat16(w.z), h3 = __float2bfloat16(w.w);
            uint32_t* dh = (uint32_t*)sBh + r * SROW + v * 2;
            uint32_t* dl = (uint32_t*)sBl + r * SROW + v * 2;
            __nv_bfloat162 p0 = __halves2bfloat162(h0, h1);
            __nv_bfloat162 p1 = __halves2bfloat162(h2, h3);
            dh[0] = *(uint32_t*)&p0; dh[1] = *(uint32_t*)&p1;
            __nv_bfloat162 q0 = __floats2bfloat162_rn(w.x - __bfloat162float(h0), w.y - __bfloat162float(h1));
            __nv_bfloat162 q1 = __floats2bfloat162_rn(w.z - __bfloat162float(h2), w.w - __bfloat162float(h3));
            dl[0] = *(uint32_t*)&q0; dl[1] = *(uint32_t*)&q1;
        }
        __syncthreads();
#pragma unroll
        for (int ks = 0; ks < 2; ks++) {
            uint32_t ah[4], al_[4], bh[8][2], bl[8][2];
            {
                int r = wm * 16 + g;
                const uint32_t* p0 = (const uint32_t*)sAh + r * SROW + ks * 8 + c;
                const uint32_t* p1 = p0 + 8 * SROW;
                ah[0] = p0[0]; ah[1] = p1[0]; ah[2] = p0[4]; ah[3] = p1[4];
                const uint32_t* q0 = (const uint32_t*)sAl + r * SROW + ks * 8 + c;
                const uint32_t* q1 = q0 + 8 * SROW;
                al_[0] = q0[0]; al_[1] = q1[0]; al_[2] = q0[4]; al_[3] = q1[4];
            }
#pragma unroll
            for (int nt = 0; nt < 8; nt++) {
                int n = wn * 64 + nt * 8 + g;
                const uint32_t* p = (const uint32_t*)sBh + n * SROW + ks * 8 + c;
                bh[nt][0] = p[0]; bh[nt][1] = p[4];
                const uint32_t* q = (const uint32_t*)sBl + n * SROW + ks * 8 + c;
                bl[nt][0] = q[0]; bl[nt][1] = q[4];
            }
#pragma unroll
            for (int nt = 0; nt < 8; nt++) {
                mma16816(acc[nt], ah, bh[nt]);
                mma16816(acc[nt], ah, bl[nt]);
                mma16816(acc[nt], al_, bh[nt]);
            }
        }
        __syncthreads();
    }
    int m = wm * 16 + g;
#pragma unroll
    for (int nt = 0; nt < 8; nt++) {
        int n = n0 + wn * 64 + nt * 8 + c * 2;
        atomicAdd(&g_g[m * 256 + n],           acc[nt][0]);
        atomicAdd(&g_g[m * 256 + n + 1],       acc[nt][1]);
        atomicAdd(&g_g[(m + 8) * 256 + n],     acc[nt][2]);
        atomicAdd(&g_g[(m + 8) * 256 + n + 1], acc[nt][3]);
    }
}

__global__ void k_final(const float* __restrict__ Wl, const float* __restrict__ bl,
                        float* __restrict__ out) {
    __shared__ float red[256];
    int t = threadIdx.x, b = blockIdx.x;
    red[t] = g_g[b * HID + t] * Wl[t];
    __syncthreads();
    for (int o = 128; o > 0; o >>= 1) {
        if (t < o) red[t] += red[t + o];
        __syncthreads();
    }
    if (t == 0) out[b] = red[0] + bl[0];
}

// ---------------- launch ----------------
extern "C" void kernel_launch(void* const* d_in, const int* in_sizes, int n_in,
                              void* d_out, int out_size) {
    const float* x   = (const float*)d_in[0];
    const int*   ei  = (const int*)d_in[1];
    const float* ew  = (const float*)d_in[2];
    const float* Wp0 = (const float*)d_in[4],  *bp0 = (const float*)d_in[5];
    const float* Wn0 = (const float*)d_in[6],  *bn0 = (const float*)d_in[7];
    const float* Wp1 = (const float*)d_in[8],  *bp1 = (const float*)d_in[9];
    const float* Wn1 = (const float*)d_in[10], *bn1 = (const float*)d_in[11];
    const float* Wp2 = (const float*)d_in[12], *bp2 = (const float*)d_in[13];
    const float* Wn2 = (const float*)d_in[14], *bn2 = (const float*)d_in[15];
    const float* Wr  = (const float*)d_in[16], *br  = (const float*)d_in[17];
    const float* Wl  = (const float*)d_in[18], *bl  = (const float*)d_in[19];
    float* out = (float*)d_out;

    const int GEMM_SMEM = 2 * STGH * 2;   // 61440 B
    cudaFuncSetAttribute(k_gemm, cudaFuncAttributeMaxDynamicSharedMemorySize, GEMM_SMEM);

    // layer-0 GEMM in ncu capture slot
    k_splitx<<<NN, 256>>>(x);
    k_pack<<<512, 256>>>(Wp0, Wn0, bp0, bn0, 200);
    k_zero_nodes<<<(NN + 255) / 256, 256>>>();
    k_gemm<<<dim3(8, 100), 256, GEMM_SMEM>>>(7);

    // graph preprocessing
    k_decode_hist<<<NE / 256, 256>>>(ei, ew);
    k_scan1<<<50, 256>>>();
    k_scan2<<<1, 32>>>();
    k_scan3<<<50, 256>>>();
    k_scatter<<<NE / 256, 256>>>(ew);

    k_agg<<<1600, 256>>>(1);

    // layer 1
    k_pack<<<512, 256>>>(Wp1, Wn1, bp1, bn1, 256);
    k_gemm<<<dim3(8, 100), 256, GEMM_SMEM>>>(8);
    k_agg<<<1600, 256>>>(1);

    // layer 2
    k_pack<<<512, 256>>>(Wp2, Wn2, bp2, bn2, 256);
    k_gemm<<<dim3(8, 100), 256, GEMM_SMEM>>>(8);
    k_agg<<<1600, 256>>>(0);

    // readout + final
    k_ginit<<<NG, 256>>>(br);
    k_readout<<<dim3(2, 100), 256>>>(Wr);
    k_final<<<NG, 256>>>(Wl, bl, out);
}

// round 8
// speedup vs baseline: 2.3790x; 1.0503x over previous
#include <cuda_runtime.h>
#include <cuda_bf16.h>
#include <cuda_fp16.h>
#include <cstdint>

#define NN 12800
#define NE 409600
#define HID 256
#define NG 64
#define RDK 51200

// ---------------- static device scratch ----------------
__device__ int   g_src[NE];
__device__ int   g_dst[NE];
__device__ unsigned long long g_cnt64[NN];   // packed: total | pos<<21 | neg<<42
__device__ int   g_rowptr[NN + 1];
__device__ int   g_cursor[NN];
__device__ float g_invdegp[NN];
__device__ float g_invdegn[NN];
__device__ int   g_esrc[NE];
__device__ float g_ews[NE];
__device__ int   g_bsum[50];
__device__ __half g_projh[(size_t)NN * 256];   // agg-part (cols 0..255), gathered 32x
__device__ float  g_projx[(size_t)NN * 256];   // x-part (cols 256..511), read once
__device__ __nv_bfloat16 g_Ah[(size_t)NN * 256];
__device__ __nv_bfloat16 g_Al[(size_t)NN * 256];
__device__ __nv_bfloat16 g_Bh[512 * 256];
__device__ __nv_bfloat16 g_Bl[512 * 256];
__device__ float g_bias[512];
__device__ float g_g[NG * HID];

// ---------------- helpers ----------------
__device__ __forceinline__ uint32_t smem_u32(const void* p) {
    uint32_t a;
    asm("{ .reg .u64 t; cvta.to.shared.u64 t, %1; cvt.u32.u64 %0, t; }" : "=r"(a) : "l"(p));
    return a;
}
__device__ __forceinline__ void cpasync16(uint32_t dst, const void* src) {
    asm volatile("cp.async.cg.shared.global [%0], [%1], 16;" :: "r"(dst), "l"(src));
}
#define CP_COMMIT() asm volatile("cp.async.commit_group;" ::: "memory")
#define CP_WAIT(n)  asm volatile("cp.async.wait_group %0;" :: "n"(n) : "memory")
__device__ __forceinline__ void mma16816(float* d, const uint32_t* a, const uint32_t* b) {
    asm volatile("mma.sync.aligned.m16n8k16.row.col.f32.bf16.bf16.f32 "
        "{%0,%1,%2,%3},{%4,%5,%6,%7},{%8,%9},{%0,%1,%2,%3};"
        : "+f"(d[0]), "+f"(d[1]), "+f"(d[2]), "+f"(d[3])
        : "r"(a[0]), "r"(a[1]), "r"(a[2]), "r"(a[3]), "r"(b[0]), "r"(b[1]));
}
#define LDSM4(r, a) \
    asm volatile("ldmatrix.sync.aligned.m8n8.x4.shared.b16 {%0,%1,%2,%3}, [%4];" \
        : "=r"((r)[0]), "=r"((r)[1]), "=r"((r)[2]), "=r"((r)[3]) : "r"(a))

// ---------------- preprocessing ----------------
__global__ void k_zero_nodes() {
    int i = blockIdx.x * blockDim.x + threadIdx.x;
    if (i < NN) g_cnt64[i] = 0ULL;
}
__global__ void k_decode_hist(const int* __restrict__ ei, const float* __restrict__ w) {
    bool is64 = ((ei[1] | ei[3] | ei[5] | ei[7] | ei[9] | ei[11] | ei[13] | ei[15]) == 0);
    int e = blockIdx.x * blockDim.x + threadIdx.x;
    if (e >= NE) return;
    int s, d;
    if (is64) {
        const long long* q = (const long long*)ei;
        s = (int)q[e]; d = (int)q[NE + e];
    } else {
        s = ei[e]; d = ei[NE + e];
    }
    g_src[e] = s; g_dst[e] = d;
    float we = w[e];
    unsigned long long add = 1ULL;
    if (we > 0.f)      add |= (1ULL << 21);
    else if (we < 0.f) add |= (1ULL << 42);
    atomicAdd(&g_cnt64[d], add);
}
__global__ void k_scan1() {
    __shared__ int ss[256];
    int b = blockIdx.x, t = threadIdx.x;
    int idx = b * 256 + t;
    int v = (int)(g_cnt64[idx] & 0x1FFFFFULL);
    ss[t] = v; __syncthreads();
    for (int off = 1; off < 256; off <<= 1) {
        int u = 0;
        if (t >= off) u = ss[t - off];
        __syncthreads();
        if (t >= off) ss[t] += u;
        __syncthreads();
    }
    g_rowptr[idx] = ss[t] - v;
    if (t == 255) g_bsum[b] = ss[t];
}
__global__ void k_scan2() {
    if (threadIdx.x == 0) {
        int s = 0;
        for (int i = 0; i < 50; i++) { int c = g_bsum[i]; g_bsum[i] = s; s += c; }
    }
}
__global__ void k_scan3() {
    int b = blockIdx.x, t = threadIdx.x;
    int idx = b * 256 + t;
    int r = g_rowptr[idx] + g_bsum[b];
    g_rowptr[idx] = r; g_cursor[idx] = r;
    unsigned long long c = g_cnt64[idx];
    int dp = (int)((c >> 21) & 0x1FFFFFULL);
    int dn = (int)(c >> 42);
    g_invdegp[idx] = 1.f / fmaxf((float)dp, 1.f);
    g_invdegn[idx] = 1.f / fmaxf((float)dn, 1.f);
    if (idx == 0) g_rowptr[NN] = NE;
}
__global__ void k_scatter(const float* __restrict__ w) {
    int e = blockIdx.x * blockDim.x + threadIdx.x;
    if (e >= NE) return;
    int d = g_dst[e];
    int pos = atomicAdd(&g_cursor[d], 1);
    g_esrc[pos] = g_src[e];
    g_ews[pos]  = w[e];
}

// ---------------- split x into bf16 hi/lo (layer-0 A), zero-pad K to 256 ----------------
__global__ void k_splitx(const float* __restrict__ x) {
    int idx = blockIdx.x * 256 + threadIdx.x;
    int r = idx >> 8, c = idx & 255;
    float v = (c < 200) ? x[r * 200 + c] : 0.f;
    __nv_bfloat16 h = __float2bfloat16(v);
    g_Ah[idx] = h;
    g_Al[idx] = __float2bfloat16(v - __bfloat162float(h));
}

// ---------------- pack weights -> bf16 hi/lo, [n=512][k=256] ----------------
__global__ void k_pack(const float* __restrict__ Wp, const float* __restrict__ Wn,
                       const float* __restrict__ bp, const float* __restrict__ bn, int D) {
    int idx = blockIdx.x * blockDim.x + threadIdx.x;
    if (idx >= 512 * 256) return;
    int m = idx >> 8, k = idx & 255;
    int twoD = 2 * D;
    float v = 0.f;
    if (k < D) {
        if (m < 128)       v = Wp[m * twoD + k];
        else if (m < 256)  v = Wn[(m - 128) * twoD + k];
        else if (m < 384)  v = Wp[(m - 256) * twoD + D + k];
        else               v = Wn[(m - 384) * twoD + D + k];
    }
    __nv_bfloat16 h = __float2bfloat16(v);
    g_Bh[idx] = h;
    g_Bl[idx] = __float2bfloat16(v - __bfloat162float(h));
    if (k == 0)
        g_bias[m] = (m < 256) ? 0.f : ((m < 384) ? bp[m - 256] : bn[m - 384]);
}

// ---------------- GEMM: bf16x3, cp.async 2-stage; BM=128, BN=128 (R5 shape) ----------------
// grid (4, 100); 8 warps: wm in {0,1} (64 rows), wn in {0..3} (32 cols)
// blockIdx.x 0,1 -> agg cols (fp16 out); 2,3 -> x cols (fp32 out + bias)
#define PADH 40
#define ARRH (128 * PADH)
#define STGH (4 * ARRH)

__global__ void __launch_bounds__(256) k_gemm(int ktiles) {
    extern __shared__ __align__(16) __nv_bfloat16 sm[];

    int tid = threadIdx.x;
    int wid = tid >> 5, lane = tid & 31;
    int wm = wid & 1, wn = wid >> 1;
    int row0 = blockIdx.y * 128;
    int col0 = blockIdx.x * 128;
    int g = lane >> 2, c = lane & 3;

    float acc[4][4][4];
#pragma unroll
    for (int mt = 0; mt < 4; mt++)
#pragma unroll
        for (int nt = 0; nt < 4; nt++)
#pragma unroll
            for (int i = 0; i < 4; i++) acc[mt][nt][i] = 0.f;

    int lrow = lane & 15;
    int lk = (lane >> 4) * 8;
    int g8 = lane >> 3;
    int b_nt = g8 >> 1;
    int b_kh = (g8 & 1) * 8;
    int b_row = lane & 7;

    int r0 = tid >> 2, v0 = (tid & 3) * 8;
    int r1 = (tid + 256) >> 2, v1 = ((tid + 256) & 3) * 8;
    uint32_t smbase = smem_u32(sm);

    auto load_stage = [&](int kt, int s) {
        int k0 = kt * 32;
        uint32_t sb = smbase + (uint32_t)s * (STGH * 2);
        cpasync16(sb + 0 * ARRH * 2 + (r0 * PADH + v0) * 2, g_Ah + (size_t)(row0 + r0) * 256 + k0 + v0);
        cpasync16(sb + 0 * ARRH * 2 + (r1 * PADH + v1) * 2, g_Ah + (size_t)(row0 + r1) * 256 + k0 + v1);
        cpasync16(sb + 1 * ARRH * 2 + (r0 * PADH + v0) * 2, g_Al + (size_t)(row0 + r0) * 256 + k0 + v0);
        cpasync16(sb + 1 * ARRH * 2 + (r1 * PADH + v1) * 2, g_Al + (size_t)(row0 + r1) * 256 + k0 + v1);
        cpasync16(sb + 2 * ARRH * 2 + (r0 * PADH + v0) * 2, g_Bh + (size_t)(col0 + r0) * 256 + k0 + v0);
        cpasync16(sb + 2 * ARRH * 2 + (r1 * PADH + v1) * 2, g_Bh + (size_t)(col0 + r1) * 256 + k0 + v1);
        cpasync16(sb + 3 * ARRH * 2 + (r0 * PADH + v0) * 2, g_Bl + (size_t)(col0 + r0) * 256 + k0 + v0);
        cpasync16(sb + 3 * ARRH * 2 + (r1 * PADH + v1) * 2, g_Bl + (size_t)(col0 + r1) * 256 + k0 + v1);
        CP_COMMIT();
    };

    load_stage(0, 0);

    for (int kt = 0; kt < ktiles; kt++) {
        int s = kt & 1;
        bool more = (kt + 1 < ktiles);
        if (more) load_stage(kt + 1, s ^ 1);
        if (more) { CP_WAIT(1); } else { CP_WAIT(0); }
        __syncthreads();

        const __nv_bfloat16* sAh = sm + s * STGH;
        const __nv_bfloat16* sAl = sAh + ARRH;
        const __nv_bfloat16* sBh = sAl + ARRH;
        const __nv_bfloat16* sBl = sBh + ARRH;

#pragma unroll
        for (int ks = 0; ks < 2; ks++) {
            uint32_t ah[4][4], al_[4][4], bh[4][2], bl[4][2];
#pragma unroll
            for (int mt = 0; mt < 4; mt++) {
                int r = wm * 64 + mt * 16 + lrow;
                LDSM4(ah[mt], smem_u32(sAh + r * PADH + ks * 16 + lk));
                LDSM4(al_[mt], smem_u32(sAl + r * PADH + ks * 16 + lk));
            }
#pragma unroll
            for (int np = 0; np < 2; np++) {
                int n = wn * 32 + (np * 2 + b_nt) * 8 + b_row;
                uint32_t r4[4];
                LDSM4(r4, smem_u32(sBh + n * PADH + ks * 16 + b_kh));
                bh[np*2][0] = r4[0]; bh[np*2][1] = r4[1];
                bh[np*2+1][0] = r4[2]; bh[np*2+1][1] = r4[3];
                LDSM4(r4, smem_u32(sBl + n * PADH + ks * 16 + b_kh));
                bl[np*2][0] = r4[0]; bl[np*2][1] = r4[1];
                bl[np*2+1][0] = r4[2]; bl[np*2+1][1] = r4[3];
            }
#pragma unroll
            for (int mt = 0; mt < 4; mt++)
#pragma unroll
                for (int nt = 0; nt < 4; nt++) {
                    mma16816(acc[mt][nt], ah[mt], bh[nt]);
                    mma16816(acc[mt][nt], ah[mt], bl[nt]);
                    mma16816(acc[mt][nt], al_[mt], bh[nt]);
                }
        }
        __syncthreads();
    }

    // store: agg cols -> fp16 (bias=0 there); x cols -> fp32 + bias
    if (col0 < 256) {
#pragma unroll
        for (int mt = 0; mt < 4; mt++) {
            int row = row0 + wm * 64 + mt * 16 + g;
#pragma unroll
            for (int nt = 0; nt < 4; nt++) {
                int col = col0 + wn * 32 + nt * 8 + 2 * c;
                __half2 o0 = __floats2half2_rn(acc[mt][nt][0], acc[mt][nt][1]);
                __half2 o1 = __floats2half2_rn(acc[mt][nt][2], acc[mt][nt][3]);
                *(__half2*)&g_projh[(size_t)row * 256 + col] = o0;
                *(__half2*)&g_projh[(size_t)(row + 8) * 256 + col] = o1;
            }
        }
    } else {
#pragma unroll
        for (int mt = 0; mt < 4; mt++) {
            int row = row0 + wm * 64 + mt * 16 + g;
#pragma unroll
            for (int nt = 0; nt < 4; nt++) {
                int col = col0 + wn * 32 + nt * 8 + 2 * c;
                float2 bb = *(const float2*)&g_bias[col];
                float2 o0, o1;
                o0.x = acc[mt][nt][0] + bb.x; o0.y = acc[mt][nt][1] + bb.y;
                o1.x = acc[mt][nt][2] + bb.x; o1.y = acc[mt][nt][3] + bb.y;
                *(float2*)&g_projx[(size_t)row * 256 + (col - 256)] = o0;
                *(float2*)&g_projx[(size_t)(row + 8) * 256 + (col - 256)] = o1;
            }
        }
    }
}

// ---------------- aggregation: fp16 gathers, fp32 accumulate ----------------
__global__ void k_agg(int lrelu) {
    int gw = (blockIdx.x * blockDim.x + threadIdx.x) >> 5;
    if (gw >= NN) return;
    int lane = threadIdx.x & 31;
    int co = lane * 4;
    int s0 = g_rowptr[gw], s1 = g_rowptr[gw + 1];
    float4 ap = make_float4(0, 0, 0, 0), an = make_float4(0, 0, 0, 0);
    int e = s0;
    for (; e + 2 <= s1; e += 2) {
        int sa = g_esrc[e],     sb = g_esrc[e + 1];
        float wa = g_ews[e],    wb = g_ews[e + 1];
        uint2 ra = *(const uint2*)(g_projh + (size_t)sa * 256 + (wa > 0.f ? 0 : 128) + co);
        uint2 rb = *(const uint2*)(g_projh + (size_t)sb * 256 + (wb > 0.f ? 0 : 128) + co);
        float2 a01 = __half22float2(*(__half2*)&ra.x);
        float2 a23 = __half22float2(*(__half2*)&ra.y);
        float2 b01 = __half22float2(*(__half2*)&rb.x);
        float2 b23 = __half22float2(*(__half2*)&rb.y);
        float aa = fabsf(wa), ab = fabsf(wb);
        if (wa > 0.f) {
            ap.x += aa * a01.x; ap.y += aa * a01.y; ap.z += aa * a23.x; ap.w += aa * a23.y;
        } else {
            an.x += aa * a01.x; an.y += aa * a01.y; an.z += aa * a23.x; an.w += aa * a23.y;
        }
        if (wb > 0.f) {
            ap.x += ab * b01.x; ap.y += ab * b01.y; ap.z += ab * b23.x; ap.w += ab * b23.y;
        } else {
            an.x += ab * b01.x; an.y += ab * b01.y; an.z += ab * b23.x; an.w += ab * b23.y;
        }
    }
    if (e < s1) {
        int sa = g_esrc[e];
        float wa = g_ews[e];
        uint2 ra = *(const uint2*)(g_projh + (size_t)sa * 256 + (wa > 0.f ? 0 : 128) + co);
        float2 a01 = __half22float2(*(__half2*)&ra.x);
        float2 a23 = __half22float2(*(__half2*)&ra.y);
        float aa = fabsf(wa);
        if (wa > 0.f) {
            ap.x += aa * a01.x; ap.y += aa * a01.y; ap.z += aa * a23.x; ap.w += aa * a23.y;
        } else {
            an.x += aa * a01.x; an.y += aa * a01.y; an.z += aa * a23.x; an.w += aa * a23.y;
        }
    }
    float ip = g_invdegp[gw], in_ = g_invdegn[gw];
    float4 xp = *(const float4*)(g_projx + (size_t)gw * 256 + co);
    float4 xn = *(const float4*)(g_projx + (size_t)gw * 256 + 128 + co);
    float hv[8];
    hv[0] = ap.x * ip + xp.x; hv[1] = ap.y * ip + xp.y;
    hv[2] = ap.z * ip + xp.z; hv[3] = ap.w * ip + xp.w;
    hv[4] = an.x * in_ + xn.x; hv[5] = an.y * in_ + xn.y;
    hv[6] = an.z * in_ + xn.z; hv[7] = an.w * in_ + xn.w;
    if (lrelu) {
#pragma unroll
        for (int i = 0; i < 8; i++) hv[i] = hv[i] > 0.f ? hv[i] : 0.01f * hv[i];
    }
    __nv_bfloat16 hh[8], hl[8];
#pragma unroll
    for (int i = 0; i < 8; i++) {
        hh[i] = __float2bfloat16(hv[i]);
        hl[i] = __float2bfloat16(hv[i] - __bfloat162float(hh[i]));
    }
    size_t base = (size_t)gw * 256;
    *(uint2*)(g_Ah + base + co)       = *(uint2*)&hh[0];
    *(uint2*)(g_Ah + base + 128 + co) = *(uint2*)&hh[4];
    *(uint2*)(g_Al + base + co)       = *(uint2*)&hl[0];
    *(uint2*)(g_Al + base + 128 + co) = *(uint2*)&hl[4];
}

// ---------------- readout ----------------
__global__ void k_ginit(const float* __restrict__ br) {
    g_g[blockIdx.x * HID + threadIdx.x] = br[threadIdx.x];
}

#define SROW 18

// grid (2, 100): n-tile 128, k-chunk 512
__global__ void __launch_bounds__(256) k_readout(const float* __restrict__ Wr) {
    __shared__ __nv_bfloat16 sAh[64][36], sAl[64][36];
    __shared__ __nv_bfloat16 sBh[128][36], sBl[128][36];
    int tid = threadIdx.x;
    int wid = tid >> 5, lane = tid & 31;
    int wm = wid & 3, wn = wid >> 2;
    int g = lane >> 2, c = lane & 3;
    int n0 = blockIdx.x * 128;
    int kbase = blockIdx.y * 512;

    float acc[8][4];
#pragma unroll
    for (int nt = 0; nt < 8; nt++)
#pragma unroll
        for (int i = 0; i < 4; i++) acc[nt][i] = 0.f;

    for (int kt = 0; kt < 16; kt++) {
        int k0 = kbase + kt * 32;
        {
            int r = tid >> 2, v = tid & 3;
            uint4 h = *(const uint4*)(g_Ah + (size_t)r * RDK + k0 + v * 8);
            uint4 l = *(const uint4*)(g_Al + (size_t)r * RDK + k0 + v * 8);
            uint32_t* dh = (uint32_t*)sAh + r * SROW + v * 4;
            uint32_t* dl = (uint32_t*)sAl + r * SROW + v * 4;
            dh[0] = h.x; dh[1] = h.y; dh[2] = h.z; dh[3] = h.w;
            dl[0] = l.x; dl[1] = l.y; dl[2] = l.z; dl[3] = l.w;
        }
#pragma unroll
        for (int i = 0; i < 4; i++) {
            int idx = tid + i * 256;
            int r = idx >> 3, v = idx & 7;
            float4 w = *(const float4*)(Wr + (size_t)(n0 + r) * RDK + k0 + v * 4);
            __nv_bfloat16 h0 = __float2bfloat16(w.x), h1 = __float2bfloat16(w.y);
            __nv_bfloat16 h2 = __float2bfloat16(w.z), h3 = __float2bfloat16(w.w);
            uint32_t* dh = (uint32_t*)sBh + r * SROW + v * 2;
            uint32_t* dl = (uint32_t*)sBl + r * SROW + v * 2;
            __nv_bfloat162 p0 = __halves2bfloat162(h0, h1);
            __nv_bfloat162 p1 = __halves2bfloat162(h2, h3);
            dh[0] = *(uint32_t*)&p0; dh[1] = *(uint32_t*)&p1;
            __nv_bfloat162 q0 = __floats2bfloat162_rn(w.x - __bfloat162float(h0), w.y - __bfloat162float(h1));
            __nv_bfloat162 q1 = __floats2bfloat162_rn(w.z - __bfloat162float(h2), w.w - __bfloat162float(h3));
            dl[0] = *(uint32_t*)&q0; dl[1] = *(uint32_t*)&q1;
        }
        __syncthreads();
#pragma unroll
        for (int ks = 0; ks < 2; ks++) {
            uint32_t ah[4], al_[4], bh[8][2], bl[8][2];
            {
                int r = wm * 16 + g;
                const uint32_t* p0 = (const uint32_t*)sAh + r * SROW + ks * 8 + c;
                const uint32_t* p1 = p0 + 8 * SROW;
                ah[0] = p0[0]; ah[1] = p1[0]; ah[2] = p0[4]; ah[3] = p1[4];
                const uint32_t* q0 = (const uint32_t*)sAl + r * SROW + ks * 8 + c;
                const uint32_t* q1 = q0 + 8 * SROW;
                al_[0] = q0[0]; al_[1] = q1[0]; al_[2] = q0[4]; al_[3] = q1[4];
            }
#pragma unroll
            for (int nt = 0; nt < 8; nt++) {
                int n = wn * 64 + nt * 8 + g;
                const uint32_t* p = (const uint32_t*)sBh + n * SROW + ks * 8 + c;
                bh[nt][0] = p[0]; bh[nt][1] = p[4];
                const uint32_t* q = (const uint32_t*)sBl + n * SROW + ks * 8 + c;
                bl[nt][0] = q[0]; bl[nt][1] = q[4];
            }
#pragma unroll
            for (int nt = 0; nt < 8; nt++) {
                mma16816(acc[nt], ah, bh[nt]);
                mma16816(acc[nt], ah, bl[nt]);
                mma16816(acc[nt], al_, bh[nt]);
            }
        }
        __syncthreads();
    }
    int m = wm * 16 + g;
#pragma unroll
    for (int nt = 0; nt < 8; nt++) {
        int n = n0 + wn * 64 + nt * 8 + c * 2;
        atomicAdd(&g_g[m * 256 + n],           acc[nt][0]);
        atomicAdd(&g_g[m * 256 + n + 1],       acc[nt][1]);
        atomicAdd(&g_g[(m + 8) * 256 + n],     acc[nt][2]);
        atomicAdd(&g_g[(m + 8) * 256 + n + 1], acc[nt][3]);
    }
}

__global__ void k_final(const float* __restrict__ Wl, const float* __restrict__ bl,
                        float* __restrict__ out) {
    __shared__ float red[256];
    int t = threadIdx.x, b = blockIdx.x;
    red[t] = g_g[b * HID + t] * Wl[t];
    __syncthreads();
    for (int o = 128; o > 0; o >>= 1) {
        if (t < o) red[t] += red[t + o];
        __syncthreads();
    }
    if (t == 0) out[b] = red[0] + bl[0];
}

// ---------------- launch ----------------
extern "C" void kernel_launch(void* const* d_in, const int* in_sizes, int n_in,
                              void* d_out, int out_size) {
    const float* x   = (const float*)d_in[0];
    const int*   ei  = (const int*)d_in[1];
    const float* ew  = (const float*)d_in[2];
    const float* Wp0 = (const float*)d_in[4],  *bp0 = (const float*)d_in[5];
    const float* Wn0 = (const float*)d_in[6],  *bn0 = (const float*)d_in[7];
    const float* Wp1 = (const float*)d_in[8],  *bp1 = (const float*)d_in[9];
    const float* Wn1 = (const float*)d_in[10], *bn1 = (const float*)d_in[11];
    const float* Wp2 = (const float*)d_in[12], *bp2 = (const float*)d_in[13];
    const float* Wn2 = (const float*)d_in[14], *bn2 = (const float*)d_in[15];
    const float* Wr  = (const float*)d_in[16], *br  = (const float*)d_in[17];
    const float* Wl  = (const float*)d_in[18], *bl  = (const float*)d_in[19];
    float* out = (float*)d_out;

    const int GEMM_SMEM = 2 * STGH * 2;   // 81920 B
    cudaFuncSetAttribute(k_gemm, cudaFuncAttributeMaxDynamicSharedMemorySize, GEMM_SMEM);

    // layer-0 GEMM in ncu capture slot
    k_splitx<<<NN, 256>>>(x);
    k_pack<<<512, 256>>>(Wp0, Wn0, bp0, bn0, 200);
    k_zero_nodes<<<(NN + 255) / 256, 256>>>();
    k_gemm<<<dim3(4, 100), 256, GEMM_SMEM>>>(7);

    // graph preprocessing
    k_decode_hist<<<NE / 256, 256>>>(ei, ew);
    k_scan1<<<50, 256>>>();
    k_scan2<<<1, 32>>>();
    k_scan3<<<50, 256>>>();
    k_scatter<<<NE / 256, 256>>>(ew);

    k_agg<<<1600, 256>>>(1);

    // layer 1
    k_pack<<<512, 256>>>(Wp1, Wn1, bp1, bn1, 256);
    k_gemm<<<dim3(4, 100), 256, GEMM_SMEM>>>(8);
    k_agg<<<1600, 256>>>(1);

    // layer 2
    k_pack<<<512, 256>>>(Wp2, Wn2, bp2, bn2, 256);
    k_gemm<<<dim3(4, 100), 256, GEMM_SMEM>>>(8);
    k_agg<<<1600, 256>>>(0);

    // readout + final
    k_ginit<<<NG, 256>>>(br);
    k_readout<<<dim3(2, 100), 256>>>(Wr);
    k_final<<<NG, 256>>>(Wl, bl, out);
}

// round 9
// speedup vs baseline: 2.5210x; 1.0597x over previous
#include <cuda_runtime.h>
#include <cuda_bf16.h>
#include <cuda_fp16.h>
#include <cstdint>

#define NN 12800
#define NE 409600
#define HID 256
#define NG 64
#define RDK 51200

// ---------------- static device scratch ----------------
__device__ int   g_src[NE];
__device__ int   g_dst[NE];
__device__ unsigned long long g_cnt64[NN];   // packed: total | pos<<21 | neg<<42 (self-cleaned)
__device__ int   g_rowptr[NN + 1];
__device__ int   g_cursor[NN];
__device__ float g_invdegp[NN];
__device__ float g_invdegn[NN];
__device__ int   g_esrc[NE];
__device__ float g_ews[NE];
__device__ int   g_bsum[50];
__device__ __half g_projh[(size_t)NN * 256];   // agg-part (cols 0..255), gathered 32x
__device__ float  g_projx[(size_t)NN * 256];   // x-part (cols 256..511), read once
__device__ __nv_bfloat16 g_Ah[(size_t)NN * 256];
__device__ __nv_bfloat16 g_Al[(size_t)NN * 256];
__device__ __nv_bfloat16 g_Bh[3 * 512 * 256];  // per-layer packed weights hi
__device__ __nv_bfloat16 g_Bl[3 * 512 * 256];  // per-layer packed weights lo
__device__ float g_bias[3 * 512];
__device__ float g_g[NG * HID];

// ---------------- helpers ----------------
__device__ __forceinline__ uint32_t smem_u32(const void* p) {
    uint32_t a;
    asm("{ .reg .u64 t; cvta.to.shared.u64 t, %1; cvt.u32.u64 %0, t; }" : "=r"(a) : "l"(p));
    return a;
}
__device__ __forceinline__ void cpasync16(uint32_t dst, const void* src) {
    asm volatile("cp.async.cg.shared.global [%0], [%1], 16;" :: "r"(dst), "l"(src));
}
#define CP_COMMIT() asm volatile("cp.async.commit_group;" ::: "memory")
#define CP_WAIT(n)  asm volatile("cp.async.wait_group %0;" :: "n"(n) : "memory")
__device__ __forceinline__ void mma16816(float* d, const uint32_t* a, const uint32_t* b) {
    asm volatile("mma.sync.aligned.m16n8k16.row.col.f32.bf16.bf16.f32 "
        "{%0,%1,%2,%3},{%4,%5,%6,%7},{%8,%9},{%0,%1,%2,%3};"
        : "+f"(d[0]), "+f"(d[1]), "+f"(d[2]), "+f"(d[3])
        : "r"(a[0]), "r"(a[1]), "r"(a[2]), "r"(a[3]), "r"(b[0]), "r"(b[1]));
}
#define LDSM4(r, a) \
    asm volatile("ldmatrix.sync.aligned.m8n8.x4.shared.b16 {%0,%1,%2,%3}, [%4];" \
        : "=r"((r)[0]), "=r"((r)[1]), "=r"((r)[2]), "=r"((r)[3]) : "r"(a))

// ---------------- preprocessing ----------------
__global__ void k_decode_hist(const int* __restrict__ ei, const float* __restrict__ w) {
    bool is64 = ((ei[1] | ei[3] | ei[5] | ei[7] | ei[9] | ei[11] | ei[13] | ei[15]) == 0);
    int e = blockIdx.x * blockDim.x + threadIdx.x;
    if (e >= NE) return;
    int s, d;
    if (is64) {
        const long long* q = (const long long*)ei;
        s = (int)q[e]; d = (int)q[NE + e];
    } else {
        s = ei[e]; d = ei[NE + e];
    }
    g_src[e] = s; g_dst[e] = d;
    float we = w[e];
    unsigned long long add = 1ULL;
    if (we > 0.f)      add |= (1ULL << 21);
    else if (we < 0.f) add |= (1ULL << 42);
    atomicAdd(&g_cnt64[d], add);
}
__global__ void k_scan1() {
    __shared__ int ss[256];
    int b = blockIdx.x, t = threadIdx.x;
    int idx = b * 256 + t;
    int v = (int)(g_cnt64[idx] & 0x1FFFFFULL);
    ss[t] = v; __syncthreads();
    for (int off = 1; off < 256; off <<= 1) {
        int u = 0;
        if (t >= off) u = ss[t - off];
        __syncthreads();
        if (t >= off) ss[t] += u;
        __syncthreads();
    }
    g_rowptr[idx] = ss[t] - v;   // local exclusive
    if (t == 255) g_bsum[b] = ss[t];
}
// scan3: adds cross-block offset (computed in-block), emits invdeg, self-cleans cnt64
__global__ void k_scan3() {
    __shared__ int s_off;
    int b = blockIdx.x, t = threadIdx.x;
    if (t == 0) {
        int s = 0;
        for (int i = 0; i < b; i++) s += g_bsum[i];
        s_off = s;
    }
    __syncthreads();
    int idx = b * 256 + t;
    int r = g_rowptr[idx] + s_off;
    g_rowptr[idx] = r; g_cursor[idx] = r;
    unsigned long long c = g_cnt64[idx];
    g_cnt64[idx] = 0ULL;                       // self-clean for next invocation
    int dp = (int)((c >> 21) & 0x1FFFFFULL);
    int dn = (int)(c >> 42);
    g_invdegp[idx] = 1.f / fmaxf((float)dp, 1.f);
    g_invdegn[idx] = 1.f / fmaxf((float)dn, 1.f);
    if (idx == 0) g_rowptr[NN] = NE;
}
__global__ void k_scatter(const float* __restrict__ w) {
    int e = blockIdx.x * blockDim.x + threadIdx.x;
    if (e >= NE) return;
    int d = g_dst[e];
    int pos = atomicAdd(&g_cursor[d], 1);
    g_esrc[pos] = g_src[e];
    g_ews[pos]  = w[e];
}

// ---------------- split x into bf16 hi/lo (layer-0 A), zero-pad K to 256 ----------------
__global__ void k_splitx(const float* __restrict__ x) {
    int idx = blockIdx.x * 256 + threadIdx.x;
    int r = idx >> 8, c = idx & 255;
    float v = (c < 200) ? x[r * 200 + c] : 0.f;
    __nv_bfloat16 h = __float2bfloat16(v);
    g_Ah[idx] = h;
    g_Al[idx] = __float2bfloat16(v - __bfloat162float(h));
}

// ---------------- pack weights -> bf16 hi/lo, [n=512][k=256], per-layer slot ----------------
__global__ void k_pack(const float* __restrict__ Wp, const float* __restrict__ Wn,
                       const float* __restrict__ bp, const float* __restrict__ bn,
                       int D, int layer) {
    int idx = blockIdx.x * blockDim.x + threadIdx.x;
    if (idx >= 512 * 256) return;
    int m = idx >> 8, k = idx & 255;
    int twoD = 2 * D;
    float v = 0.f;
    if (k < D) {
        if (m < 128)       v = Wp[m * twoD + k];
        else if (m < 256)  v = Wn[(m - 128) * twoD + k];
        else if (m < 384)  v = Wp[(m - 256) * twoD + D + k];
        else               v = Wn[(m - 384) * twoD + D + k];
    }
    size_t off = (size_t)layer * 512 * 256 + idx;
    __nv_bfloat16 h = __float2bfloat16(v);
    g_Bh[off] = h;
    g_Bl[off] = __float2bfloat16(v - __bfloat162float(h));
    if (k == 0)
        g_bias[layer * 512 + m] = (m < 256) ? 0.f : ((m < 384) ? bp[m - 256] : bn[m - 384]);
}

// ---------------- GEMM: bf16x3, cp.async 2-stage; BM=128, BN=128 ----------------
// grid (4, 100); 8 warps: wm in {0,1} (64 rows), wn in {0..3} (32 cols)
// blockIdx.x 0,1 -> agg cols (fp16 out); 2,3 -> x cols (fp32 out + bias)
#define PADH 40
#define ARRH (128 * PADH)
#define STGH (4 * ARRH)

__global__ void __launch_bounds__(256) k_gemm(int ktiles, int layer) {
    extern __shared__ __align__(16) __nv_bfloat16 sm[];

    const __nv_bfloat16* __restrict__ Bh = g_Bh + (size_t)layer * 512 * 256;
    const __nv_bfloat16* __restrict__ Bl = g_Bl + (size_t)layer * 512 * 256;
    const float* __restrict__ bias = g_bias + layer * 512;

    int tid = threadIdx.x;
    int wid = tid >> 5, lane = tid & 31;
    int wm = wid & 1, wn = wid >> 1;
    int row0 = blockIdx.y * 128;
    int col0 = blockIdx.x * 128;
    int g = lane >> 2, c = lane & 3;

    float acc[4][4][4];
#pragma unroll
    for (int mt = 0; mt < 4; mt++)
#pragma unroll
        for (int nt = 0; nt < 4; nt++)
#pragma unroll
            for (int i = 0; i < 4; i++) acc[mt][nt][i] = 0.f;

    int lrow = lane & 15;
    int lk = (lane >> 4) * 8;
    int g8 = lane >> 3;
    int b_nt = g8 >> 1;
    int b_kh = (g8 & 1) * 8;
    int b_row = lane & 7;

    int r0 = tid >> 2, v0 = (tid & 3) * 8;
    int r1 = (tid + 256) >> 2, v1 = ((tid + 256) & 3) * 8;
    uint32_t smbase = smem_u32(sm);

    auto load_stage = [&](int kt, int s) {
        int k0 = kt * 32;
        uint32_t sb = smbase + (uint32_t)s * (STGH * 2);
        cpasync16(sb + 0 * ARRH * 2 + (r0 * PADH + v0) * 2, g_Ah + (size_t)(row0 + r0) * 256 + k0 + v0);
        cpasync16(sb + 0 * ARRH * 2 + (r1 * PADH + v1) * 2, g_Ah + (size_t)(row0 + r1) * 256 + k0 + v1);
        cpasync16(sb + 1 * ARRH * 2 + (r0 * PADH + v0) * 2, g_Al + (size_t)(row0 + r0) * 256 + k0 + v0);
        cpasync16(sb + 1 * ARRH * 2 + (r1 * PADH + v1) * 2, g_Al + (size_t)(row0 + r1) * 256 + k0 + v1);
        cpasync16(sb + 2 * ARRH * 2 + (r0 * PADH + v0) * 2, Bh + (size_t)(col0 + r0) * 256 + k0 + v0);
        cpasync16(sb + 2 * ARRH * 2 + (r1 * PADH + v1) * 2, Bh + (size_t)(col0 + r1) * 256 + k0 + v1);
        cpasync16(sb + 3 * ARRH * 2 + (r0 * PADH + v0) * 2, Bl + (size_t)(col0 + r0) * 256 + k0 + v0);
        cpasync16(sb + 3 * ARRH * 2 + (r1 * PADH + v1) * 2, Bl + (size_t)(col0 + r1) * 256 + k0 + v1);
        CP_COMMIT();
    };

    load_stage(0, 0);

    for (int kt = 0; kt < ktiles; kt++) {
        int s = kt & 1;
        bool more = (kt + 1 < ktiles);
        if (more) load_stage(kt + 1, s ^ 1);
        if (more) { CP_WAIT(1); } else { CP_WAIT(0); }
        __syncthreads();

        const __nv_bfloat16* sAh = sm + s * STGH;
        const __nv_bfloat16* sAl = sAh + ARRH;
        const __nv_bfloat16* sBh = sAl + ARRH;
        const __nv_bfloat16* sBl = sBh + ARRH;

#pragma unroll
        for (int ks = 0; ks < 2; ks++) {
            uint32_t ah[4][4], al_[4][4], bh[4][2], bl[4][2];
#pragma unroll
            for (int mt = 0; mt < 4; mt++) {
                int r = wm * 64 + mt * 16 + lrow;
                LDSM4(ah[mt], smem_u32(sAh + r * PADH + ks * 16 + lk));
                LDSM4(al_[mt], smem_u32(sAl + r * PADH + ks * 16 + lk));
            }
#pragma unroll
            for (int np = 0; np < 2; np++) {
                int n = wn * 32 + (np * 2 + b_nt) * 8 + b_row;
                uint32_t r4[4];
                LDSM4(r4, smem_u32(sBh + n * PADH + ks * 16 + b_kh));
                bh[np*2][0] = r4[0]; bh[np*2][1] = r4[1];
                bh[np*2+1][0] = r4[2]; bh[np*2+1][1] = r4[3];
                LDSM4(r4, smem_u32(sBl + n * PADH + ks * 16 + b_kh));
                bl[np*2][0] = r4[0]; bl[np*2][1] = r4[1];
                bl[np*2+1][0] = r4[2]; bl[np*2+1][1] = r4[3];
            }
#pragma unroll
            for (int mt = 0; mt < 4; mt++)
#pragma unroll
                for (int nt = 0; nt < 4; nt++) {
                    mma16816(acc[mt][nt], ah[mt], bh[nt]);
                    mma16816(acc[mt][nt], ah[mt], bl[nt]);
                    mma16816(acc[mt][nt], al_[mt], bh[nt]);
                }
        }
        __syncthreads();
    }

    // store: agg cols -> fp16 (bias=0 there); x cols -> fp32 + bias
    if (col0 < 256) {
#pragma unroll
        for (int mt = 0; mt < 4; mt++) {
            int row = row0 + wm * 64 + mt * 16 + g;
#pragma unroll
            for (int nt = 0; nt < 4; nt++) {
                int col = col0 + wn * 32 + nt * 8 + 2 * c;
                __half2 o0 = __floats2half2_rn(acc[mt][nt][0], acc[mt][nt][1]);
                __half2 o1 = __floats2half2_rn(acc[mt][nt][2], acc[mt][nt][3]);
                *(__half2*)&g_projh[(size_t)row * 256 + col] = o0;
                *(__half2*)&g_projh[(size_t)(row + 8) * 256 + col] = o1;
            }
        }
    } else {
#pragma unroll
        for (int mt = 0; mt < 4; mt++) {
            int row = row0 + wm * 64 + mt * 16 + g;
#pragma unroll
            for (int nt = 0; nt < 4; nt++) {
                int col = col0 + wn * 32 + nt * 8 + 2 * c;
                float2 bb = *(const float2*)&bias[col];
                float2 o0, o1;
                o0.x = acc[mt][nt][0] + bb.x; o0.y = acc[mt][nt][1] + bb.y;
                o1.x = acc[mt][nt][2] + bb.x; o1.y = acc[mt][nt][3] + bb.y;
                *(float2*)&g_projx[(size_t)row * 256 + (col - 256)] = o0;
                *(float2*)&g_projx[(size_t)(row + 8) * 256 + (col - 256)] = o1;
            }
        }
    }
}

// ---------------- aggregation: fp16 gathers, fp32 accumulate ----------------
__global__ void k_agg(int lrelu) {
    int gw = (blockIdx.x * blockDim.x + threadIdx.x) >> 5;
    if (gw >= NN) return;
    int lane = threadIdx.x & 31;
    int co = lane * 4;
    int s0 = g_rowptr[gw], s1 = g_rowptr[gw + 1];
    float4 ap = make_float4(0, 0, 0, 0), an = make_float4(0, 0, 0, 0);
    int e = s0;
    for (; e + 2 <= s1; e += 2) {
        int sa = g_esrc[e],     sb = g_esrc[e + 1];
        float wa = g_ews[e],    wb = g_ews[e + 1];
        uint2 ra = *(const uint2*)(g_projh + (size_t)sa * 256 + (wa > 0.f ? 0 : 128) + co);
        uint2 rb = *(const uint2*)(g_projh + (size_t)sb * 256 + (wb > 0.f ? 0 : 128) + co);
        float2 a01 = __half22float2(*(__half2*)&ra.x);
        float2 a23 = __half22float2(*(__half2*)&ra.y);
        float2 b01 = __half22float2(*(__half2*)&rb.x);
        float2 b23 = __half22float2(*(__half2*)&rb.y);
        float aa = fabsf(wa), ab = fabsf(wb);
        if (wa > 0.f) {
            ap.x += aa * a01.x; ap.y += aa * a01.y; ap.z += aa * a23.x; ap.w += aa * a23.y;
        } else {
            an.x += aa * a01.x; an.y += aa * a01.y; an.z += aa * a23.x; an.w += aa * a23.y;
        }
        if (wb > 0.f) {
            ap.x += ab * b01.x; ap.y += ab * b01.y; ap.z += ab * b23.x; ap.w += ab * b23.y;
        } else {
            an.x += ab * b01.x; an.y += ab * b01.y; an.z += ab * b23.x; an.w += ab * b23.y;
        }
    }
    if (e < s1) {
        int sa = g_esrc[e];
        float wa = g_ews[e];
        uint2 ra = *(const uint2*)(g_projh + (size_t)sa * 256 + (wa > 0.f ? 0 : 128) + co);
        float2 a01 = __half22float2(*(__half2*)&ra.x);
        float2 a23 = __half22float2(*(__half2*)&ra.y);
        float aa = fabsf(wa);
        if (wa > 0.f) {
            ap.x += aa * a01.x; ap.y += aa * a01.y; ap.z += aa * a23.x; ap.w += aa * a23.y;
        } else {
            an.x += aa * a01.x; an.y += aa * a01.y; an.z += aa * a23.x; an.w += aa * a23.y;
        }
    }
    float ip = g_invdegp[gw], in_ = g_invdegn[gw];
    float4 xp = *(const float4*)(g_projx + (size_t)gw * 256 + co);
    float4 xn = *(const float4*)(g_projx + (size_t)gw * 256 + 128 + co);
    float hv[8];
    hv[0] = ap.x * ip + xp.x; hv[1] = ap.y * ip + xp.y;
    hv[2] = ap.z * ip + xp.z; hv[3] = ap.w * ip + xp.w;
    hv[4] = an.x * in_ + xn.x; hv[5] = an.y * in_ + xn.y;
    hv[6] = an.z * in_ + xn.z; hv[7] = an.w * in_ + xn.w;
    if (lrelu) {
#pragma unroll
        for (int i = 0; i < 8; i++) hv[i] = hv[i] > 0.f ? hv[i] : 0.01f * hv[i];
    }
    __nv_bfloat16 hh[8], hl[8];
#pragma unroll
    for (int i = 0; i < 8; i++) {
        hh[i] = __float2bfloat16(hv[i]);
        hl[i] = __float2bfloat16(hv[i] - __bfloat162float(hh[i]));
    }
    size_t base = (size_t)gw * 256;
    *(uint2*)(g_Ah + base + co)       = *(uint2*)&hh[0];
    *(uint2*)(g_Ah + base + 128 + co) = *(uint2*)&hh[4];
    *(uint2*)(g_Al + base + co)       = *(uint2*)&hl[0];
    *(uint2*)(g_Al + base + 128 + co) = *(uint2*)&hl[4];
}

// ---------------- readout ----------------
__global__ void k_ginit(const float* __restrict__ br) {
    g_g[blockIdx.x * HID + threadIdx.x] = br[threadIdx.x];
}

#define SROW 18

// grid (2, 100): n-tile 128, k-chunk 512
__global__ void __launch_bounds__(256) k_readout(const float* __restrict__ Wr) {
    __shared__ __nv_bfloat16 sAh[64][36], sAl[64][36];
    __shared__ __nv_bfloat16 sBh[128][36], sBl[128][36];
    int tid = threadIdx.x;
    int wid = tid >> 5, lane = tid & 31;
    int wm = wid & 3, wn = wid >> 2;
    int g = lane >> 2, c = lane & 3;
    int n0 = blockIdx.x * 128;
    int kbase = blockIdx.y * 512;

    float acc[8][4];
#pragma unroll
    for (int nt = 0; nt < 8; nt++)
#pragma unroll
        for (int i = 0; i < 4; i++) acc[nt][i] = 0.f;

    for (int kt = 0; kt < 16; kt++) {
        int k0 = kbase + kt * 32;
        {
            int r = tid >> 2, v = tid & 3;
            uint4 h = *(const uint4*)(g_Ah + (size_t)r * RDK + k0 + v * 8);
            uint4 l = *(const uint4*)(g_Al + (size_t)r * RDK + k0 + v * 8);
            uint32_t* dh = (uint32_t*)sAh + r * SROW + v * 4;
            uint32_t* dl = (uint32_t*)sAl + r * SROW + v * 4;
            dh[0] = h.x; dh[1] = h.y; dh[2] = h.z; dh[3] = h.w;
            dl[0] = l.x; dl[1] = l.y; dl[2] = l.z; dl[3] = l.w;
        }
#pragma unroll
        for (int i = 0; i < 4; i++) {
            int idx = tid + i * 256;
            int r = idx >> 3, v = idx & 7;
            float4 w = *(const float4*)(Wr + (size_t)(n0 + r) * RDK + k0 + v * 4);
            __nv_bfloat16 h0 = __float2bfloat16(w.x), h1 = __float2bfloat16(w.y);
            __nv_bfloat16 h2 = __float2bfloat16(w.z), h3 = __float2bfloat16(w.w);
            uint32_t* dh = (uint32_t*)sBh + r * SROW + v * 2;
            uint32_t* dl = (uint32_t*)sBl + r * SROW + v * 2;
            __nv_bfloat162 p0 = __halves2bfloat162(h0, h1);
            __nv_bfloat162 p1 = __halves2bfloat162(h2, h3);
            dh[0] = *(uint32_t*)&p0; dh[1] = *(uint32_t*)&p1;
            __nv_bfloat162 q0 = __floats2bfloat162_rn(w.x - __bfloat162float(h0), w.y - __bfloat162float(h1));
            __nv_bfloat162 q1 = __floats2bfloat162_rn(w.z - __bfloat162float(h2), w.w - __bfloat162float(h3));
            dl[0] = *(uint32_t*)&q0; dl[1] = *(uint32_t*)&q1;
        }
        __syncthreads();
#pragma unroll
        for (int ks = 0; ks < 2; ks++) {
            uint32_t ah[4], al_[4], bh[8][2], bl[8][2];
            {
                int r = wm * 16 + g;
                const uint32_t* p0 = (const uint32_t*)sAh + r * SROW + ks * 8 + c;
                const uint32_t* p1 = p0 + 8 * SROW;
                ah[0] = p0[0]; ah[1] = p1[0]; ah[2] = p0[4]; ah[3] = p1[4];
                const uint32_t* q0 = (const uint32_t*)sAl + r * SROW + ks * 8 + c;
                const uint32_t* q1 = q0 + 8 * SROW;
                al_[0] = q0[0]; al_[1] = q1[0]; al_[2] = q0[4]; al_[3] = q1[4];
            }
#pragma unroll
            for (int nt = 0; nt < 8; nt++) {
                int n = wn * 64 + nt * 8 + g;
                const uint32_t* p = (const uint32_t*)sBh + n * SROW + ks * 8 + c;
                bh[nt][0] = p[0]; bh[nt][1] = p[4];
                const uint32_t* q = (const uint32_t*)sBl + n * SROW + ks * 8 + c;
                bl[nt][0] = q[0]; bl[nt][1] = q[4];
            }
#pragma unroll
            for (int nt = 0; nt < 8; nt++) {
                mma16816(acc[nt], ah, bh[nt]);
                mma16816(acc[nt], ah, bl[nt]);
                mma16816(acc[nt], al_, bh[nt]);
            }
        }
        __syncthreads();
    }
    int m = wm * 16 + g;
#pragma unroll
    for (int nt = 0; nt < 8; nt++) {
        int n = n0 + wn * 64 + nt * 8 + c * 2;
        atomicAdd(&g_g[m * 256 + n],           acc[nt][0]);
        atomicAdd(&g_g[m * 256 + n + 1],       acc[nt][1]);
        atomicAdd(&g_g[(m + 8) * 256 + n],     acc[nt][2]);
        atomicAdd(&g_g[(m + 8) * 256 + n + 1], acc[nt][3]);
    }
}

__global__ void k_final(const float* __restrict__ Wl, const float* __restrict__ bl,
                        float* __restrict__ out) {
    __shared__ float red[256];
    int t = threadIdx.x, b = blockIdx.x;
    red[t] = g_g[b * HID + t] * Wl[t];
    __syncthreads();
    for (int o = 128; o > 0; o >>= 1) {
        if (t < o) red[t] += red[t + o];
        __syncthreads();
    }
    if (t == 0) out[b] = red[0] + bl[0];
}

// ---------------- launch: forked-stream graph ----------------
extern "C" void kernel_launch(void* const* d_in, const int* in_sizes, int n_in,
                              void* d_out, int out_size) {
    const float* x   = (const float*)d_in[0];
    const int*   ei  = (const int*)d_in[1];
    const float* ew  = (const float*)d_in[2];
    const float* Wp0 = (const float*)d_in[4],  *bp0 = (const float*)d_in[5];
    const float* Wn0 = (const float*)d_in[6],  *bn0 = (const float*)d_in[7];
    const float* Wp1 = (const float*)d_in[8],  *bp1 = (const float*)d_in[9];
    const float* Wn1 = (const float*)d_in[10], *bn1 = (const float*)d_in[11];
    const float* Wp2 = (const float*)d_in[12], *bp2 = (const float*)d_in[13];
    const float* Wn2 = (const float*)d_in[14], *bn2 = (const float*)d_in[15];
    const float* Wr  = (const float*)d_in[16], *br  = (const float*)d_in[17];
    const float* Wl  = (const float*)d_in[18], *bl  = (const float*)d_in[19];
    float* out = (float*)d_out;

    const int GEMM_SMEM = 2 * STGH * 2;   // 81920 B
    cudaFuncSetAttribute(k_gemm, cudaFuncAttributeMaxDynamicSharedMemorySize, GEMM_SMEM);

    // second stream (fork/join via events; handles leaked intentionally —
    // destroying a capturing stream would invalidate the harness's capture)
    cudaStream_t s2;
    cudaStreamCreateWithFlags(&s2, cudaStreamNonBlocking);
    cudaEvent_t evF, evJ;
    cudaEventCreateWithFlags(&evF, cudaEventDisableTiming);
    cudaEventCreateWithFlags(&evJ, cudaEventDisableTiming);

    // fork
    cudaEventRecord(evF, 0);
    cudaStreamWaitEvent(s2, evF, 0);

    // stream 0: weight/feature prep + layer-0 GEMM (independent of edges)
    k_splitx<<<NN, 256>>>(x);
    k_pack<<<512, 256>>>(Wp0, Wn0, bp0, bn0, 200, 0);
    k_pack<<<512, 256>>>(Wp1, Wn1, bp1, bn1, 256, 1);
    k_pack<<<512, 256>>>(Wp2, Wn2, bp2, bn2, 256, 2);
    k_gemm<<<dim3(4, 100), 256, GEMM_SMEM>>>(7, 0);

    // stream s2: edge preprocessing (independent of GEMM chain)
    k_decode_hist<<<NE / 256, 256, 0, s2>>>(ei, ew);
    k_scan1<<<50, 256, 0, s2>>>();
    k_scan3<<<50, 256, 0, s2>>>();
    k_scatter<<<NE / 256, 256, 0, s2>>>(ew);
    k_ginit<<<NG, 256, 0, s2>>>(br);
    cudaEventRecord(evJ, s2);

    // join: aggregation needs both CSR and proj
    cudaStreamWaitEvent(0, evJ, 0);
    k_agg<<<1600, 256>>>(1);

    // layer 1
    k_gemm<<<dim3(4, 100), 256, GEMM_SMEM>>>(8, 1);
    k_agg<<<1600, 256>>>(1);

    // layer 2
    k_gemm<<<dim3(4, 100), 256, GEMM_SMEM>>>(8, 2);
    k_agg<<<1600, 256>>>(0);

    // readout + final
    k_readout<<<dim3(2, 100), 256>>>(Wr);
    k_final<<<NG, 256>>>(Wl, bl, out);
}